// round 1
// baseline (speedup 1.0000x reference)
#include <cuda_runtime.h>
#include <math.h>

#define NB 16
#define NN 2048
#define WC 64
#define NR 4
#define NI 512
#define DELTAF 1e-6f
#define TI 32

// ---- output offsets (flattened tuple order) ----
#define OFF_RV    0
#define OFF_MEM   (NB*NR*WC)                 // 4096
#define OFF_LINK  (OFF_MEM + NB*NN*WC)       // 2101248
#define OFF_PREC  (OFF_LINK + NB*NN*NN)      // 69210112
#define OFF_RW    (OFF_PREC + NB*NN)         // 69242880
#define OFF_WW    (OFF_RW + NB*NR*NN)        // 69373952
#define OFF_USAGE (OFF_WW + NB*NN)           // 69406720

// ---- device scratch ----
__device__ float g_readkeys[NB*NR*WC];
__device__ float g_rs[NB*NR];
__device__ float g_wkey[NB*WC];
__device__ float g_wstr[NB];
__device__ float g_ev[NB*WC];
__device__ float g_wv[NB*WC];
__device__ float g_fg[NB*NR];
__device__ float g_ag[NB];
__device__ float g_wg[NB];
__device__ float g_rmraw[NB*12];
__device__ float g_wcw[NB*NN];
__device__ float g_alloc[NB*NN];
__device__ float g_mnorm[NB*NN];
__device__ float g_fwd[NB*NR*NN];
__device__ float g_bwd[NB*NR*NN];
__device__ float g_rcw[NB*NR*NN];

struct CP { const float* W[10]; const float* bvec[10]; };

__device__ __forceinline__ float act_apply(int code, float v){
    switch(code){
        case 0: return tanhf(v);
        case 1: return fmaxf(v, 0.f) + log1pf(expf(-fabsf(v)));  // softplus (stable)
        case 2: return 1.f/(1.f + expf(-v));                      // sigmoid
        default: return v;
    }
}

__device__ __forceinline__ float* seg_out(int seg){
    switch(seg){
        case 0: return g_readkeys;
        case 1: return g_rs;
        case 2: return g_wkey;
        case 3: return g_wstr;
        case 4: return g_ev;
        case 5: return g_wv;
        case 6: return g_fg;
        case 7: return g_ag;
        case 8: return g_wg;
        default: return g_rmraw;
    }
}

// ---- zero fwd/bwd accumulators ----
__global__ void k_zero(){
    int id = blockIdx.x*blockDim.x + threadIdx.x;   // 65536 threads
    #pragma unroll
    for (int k = 0; k < 2; k++){
        int i = k*65536 + id;
        g_fwd[i] = 0.f;
        g_bwd[i] = 0.f;
    }
}

// ---- controller projections: one warp per output row (471 rows) ----
__global__ void k_ctrl(const float* __restrict__ x, CP cp){
    __shared__ float sx[NB*NI];
    int tid = threadIdx.x;
    for (int i = tid; i < NB*NI; i += blockDim.x) sx[i] = x[i];
    __syncthreads();
    int gw = (blockIdx.x*blockDim.x + tid) >> 5;
    int lane = tid & 31;
    if (gw >= 471) return;
    const int segStart[10] = {0,256,260,324,325,389,453,457,458,459};
    const int segLen[10]   = {256,4,64,1,64,64,4,1,1,12};
    const int segAct[10]   = {0,1,0,1,2,0,2,2,2,3};
    int seg = 0;
    for (int s = 9; s >= 0; s--){ if (gw >= segStart[s]){ seg = s; break; } }
    int rl = gw - segStart[seg];
    const float* W = cp.W[seg] + rl*NI;
    float wreg[16];
    #pragma unroll
    for (int s = 0; s < 16; s++) wreg[s] = W[s*32 + lane];
    float bias = cp.bvec[seg][rl];
    float* outp = seg_out(seg);
    int sl = segLen[seg], ac = segAct[seg];
    for (int b = 0; b < NB; b++){
        const float* xb = &sx[b*NI];
        float sum = 0.f;
        #pragma unroll
        for (int s = 0; s < 16; s++) sum += wreg[s]*xb[s*32 + lane];
        #pragma unroll
        for (int off = 16; off; off >>= 1) sum += __shfl_xor_sync(0xffffffffu, sum, off);
        if (lane == 0) outp[b*sl + rl] = act_apply(ac, sum + bias);
    }
}

// ---- usage update + retention ----
__global__ void k_usage(const float* __restrict__ u0v, const float* __restrict__ wwold,
                        const float* __restrict__ rwold, float* __restrict__ out){
    int id = blockIdx.x*blockDim.x + threadIdx.x;
    if (id >= NB*NN) return;
    int b = id >> 11, n = id & (NN-1);
    float u0 = u0v[id];
    float u = u0 + (1.f - u0)*wwold[id];
    float ret = 1.f;
    #pragma unroll
    for (int r = 0; r < NR; r++) ret *= (1.f - g_fg[b*NR+r]*rwold[(b*NR+r)*NN + n]);
    out[OFF_USAGE + id] = u*ret;
}

// ---- write content weighting (softmax over n per batch) ----
__global__ void k_wcw(const float* __restrict__ mem){
    __shared__ float skey[WC];
    __shared__ float logits[NN];
    __shared__ float rbuf[256];
    int b = blockIdx.x, tid = threadIdx.x;
    if (tid < WC) skey[tid] = g_wkey[b*WC + tid];
    __syncthreads();
    float kn2 = 0.f;
    #pragma unroll
    for (int i = 0; i < WC; i++) kn2 += skey[i]*skey[i];
    float kn = sqrtf(kn2);
    float beta = g_wstr[b];
    for (int n = tid; n < NN; n += 256){
        const float4* row = (const float4*)(mem + ((size_t)b*NN + n)*WC);
        float dot = 0.f, sq = 0.f;
        #pragma unroll
        for (int i = 0; i < WC/4; i++){
            float4 m = row[i];
            dot += m.x*skey[4*i] + m.y*skey[4*i+1] + m.z*skey[4*i+2] + m.w*skey[4*i+3];
            sq  += m.x*m.x + m.y*m.y + m.z*m.z + m.w*m.w;
        }
        logits[n] = beta*dot/(kn*sqrtf(sq) + DELTAF);
    }
    __syncthreads();
    float mx = -1e30f;
    for (int n = tid; n < NN; n += 256) mx = fmaxf(mx, logits[n]);
    rbuf[tid] = mx; __syncthreads();
    for (int s = 128; s; s >>= 1){ if (tid < s) rbuf[tid] = fmaxf(rbuf[tid], rbuf[tid+s]); __syncthreads(); }
    mx = rbuf[0]; __syncthreads();
    float sum = 0.f;
    for (int n = tid; n < NN; n += 256){ float e = expf(logits[n]-mx); logits[n] = e; sum += e; }
    rbuf[tid] = sum; __syncthreads();
    for (int s = 128; s; s >>= 1){ if (tid < s) rbuf[tid] += rbuf[tid+s]; __syncthreads(); }
    float inv = 1.f/rbuf[0];
    for (int n = tid; n < NN; n += 256) g_wcw[b*NN+n] = logits[n]*inv;
}

// ---- allocation weighting: bitonic sort + prefix product (per batch) ----
__global__ void k_alloc(const float* __restrict__ out){
    __shared__ unsigned long long keys[NN];
    __shared__ float pbuf[NN];
    int b = blockIdx.x, tid = threadIdx.x;   // 1024 threads
    for (int i = tid; i < NN; i += 1024){
        float usage = out[OFF_USAGE + b*NN + i];
        float u = DELTAF + (1.f - DELTAF)*usage;
        keys[i] = ((unsigned long long)__float_as_uint(u) << 32) | (unsigned)i;
    }
    __syncthreads();
    for (int k = 2; k <= NN; k <<= 1){
        for (int j = k >> 1; j > 0; j >>= 1){
            for (int i = tid; i < NN; i += 1024){
                int ixj = i ^ j;
                if (ixj > i){
                    bool up = ((i & k) == 0);
                    unsigned long long a = keys[i], c = keys[ixj];
                    if (up ? (a > c) : (a < c)){ keys[i] = c; keys[ixj] = a; }
                }
            }
            __syncthreads();
        }
    }
    for (int i = tid; i < NN; i += 1024) pbuf[i] = __uint_as_float((unsigned)(keys[i] >> 32));
    __syncthreads();
    for (int d = 1; d < NN; d <<= 1){
        float v1 = pbuf[tid];        float m1 = (tid >= d) ? pbuf[tid-d] : 1.f;
        int i2 = tid + 1024;
        float v2 = pbuf[i2];         float m2 = pbuf[i2-d];
        __syncthreads();
        pbuf[tid] = v1*m1; pbuf[i2] = v2*m2;
        __syncthreads();
    }
    for (int i = tid; i < NN; i += 1024){
        unsigned long long kv = keys[i];
        float u = __uint_as_float((unsigned)(kv >> 32));
        int orig = (int)(kv & 0xffffffffu);
        float ex = (i == 0) ? 1.f : pbuf[i-1];
        g_alloc[b*NN + orig] = (1.f - u)*ex;
    }
}

// ---- ww + precedence update (per batch; needs block sum of ww) ----
__global__ void k_ww(const float* __restrict__ prec_old, float* __restrict__ out){
    __shared__ float rbuf[256];
    int b = blockIdx.x, tid = threadIdx.x;
    float agv = g_ag[b], wgv = g_wg[b];
    float wwv[8];
    float s = 0.f;
    #pragma unroll
    for (int k = 0; k < 8; k++){
        int n = k*256 + tid;
        float w = wgv*(agv*g_alloc[b*NN+n] + (1.f-agv)*g_wcw[b*NN+n]);
        wwv[k] = w; s += w;
        out[OFF_WW + b*NN + n] = w;
    }
    rbuf[tid] = s; __syncthreads();
    for (int st = 128; st; st >>= 1){ if (tid < st) rbuf[tid] += rbuf[tid+st]; __syncthreads(); }
    float S = rbuf[0];
    #pragma unroll
    for (int k = 0; k < 8; k++){
        int n = k*256 + tid;
        out[OFF_PREC + b*NN + n] = (1.f - S)*prec_old[b*NN + n] + wwv[k];
    }
}

// ---- memory update + new row norms (one warp per row) ----
__global__ void k_memnew(const float* __restrict__ mem, float* __restrict__ out){
    int row = (blockIdx.x*blockDim.x + threadIdx.x) >> 5;
    int lane = threadIdx.x & 31;
    if (row >= NB*NN) return;
    int b = row >> 11;
    int w0 = lane*2;
    float2 m = *(const float2*)(mem + (size_t)row*WC + w0);
    float ww = out[OFF_WW + row];
    float e0 = g_ev[b*WC + w0], e1 = g_ev[b*WC + w0 + 1];
    float v0 = g_wv[b*WC + w0], v1 = g_wv[b*WC + w0 + 1];
    float n0 = m.x*(1.f - ww*e0) + ww*v0;
    float n1 = m.y*(1.f - ww*e1) + ww*v1;
    *(float2*)(out + OFF_MEM + (size_t)row*WC + w0) = make_float2(n0, n1);
    float sq = n0*n0 + n1*n1;
    #pragma unroll
    for (int off = 16; off; off >>= 1) sq += __shfl_xor_sync(0xffffffffu, sq, off);
    if (lane == 0) g_mnorm[row] = sqrtf(sq);
}

// ---- fused link update + fwd/bwd einsums (single pass over L) ----
__global__ void k_link(const float* __restrict__ link_old, const float* __restrict__ prec_old,
                       const float* __restrict__ rw_old, float* __restrict__ out){
    __shared__ float wwi_s[TI];
    __shared__ float rwi_s[NR][TI];
    int b = blockIdx.y;
    int i0 = blockIdx.x * TI;
    int tid = threadIdx.x;
    if (tid < TI) wwi_s[tid] = out[OFF_WW + b*NN + i0 + tid];
    if (tid < NR*TI){
        int r = tid / TI, ii = tid % TI;
        rwi_s[r][ii] = rw_old[(b*NR+r)*NN + i0 + ii];
    }
    int jb = tid * 8;
    float wwj[8], pj[8], rwj[NR][8];
    #pragma unroll
    for (int k = 0; k < 8; k++){
        wwj[k] = out[OFF_WW + b*NN + jb + k];
        pj[k]  = prec_old[b*NN + jb + k];
    }
    #pragma unroll
    for (int r = 0; r < NR; r++)
        #pragma unroll
        for (int k = 0; k < 8; k++) rwj[r][k] = rw_old[(b*NR+r)*NN + jb + k];
    float bwd[NR][8];
    #pragma unroll
    for (int r = 0; r < NR; r++)
        #pragma unroll
        for (int k = 0; k < 8; k++) bwd[r][k] = 0.f;
    __syncthreads();
    const float* Lb = link_old + ((size_t)b*NN + i0)*NN + jb;
    float* Ob = out + OFF_LINK + ((size_t)b*NN + i0)*NN + jb;
    int lane = tid & 31;
    for (int ii = 0; ii < TI; ii++){
        int i = i0 + ii;
        float wwi = wwi_s[ii];
        const float4* L4 = (const float4*)(Lb + (size_t)ii*NN);
        float4 o0 = L4[0], o1 = L4[1];
        float old[8] = {o0.x,o0.y,o0.z,o0.w,o1.x,o1.y,o1.z,o1.w};
        float nv[8];
        #pragma unroll
        for (int k = 0; k < 8; k++){
            float v = (1.f - wwi - wwj[k])*old[k] + wwi*pj[k];
            if (jb + k == i) v = 0.f;
            nv[k] = v;
        }
        float4* O4 = (float4*)(Ob + (size_t)ii*NN);
        O4[0] = make_float4(nv[0],nv[1],nv[2],nv[3]);
        O4[1] = make_float4(nv[4],nv[5],nv[6],nv[7]);
        float f[NR];
        #pragma unroll
        for (int r = 0; r < NR; r++){
            float s = 0.f;
            #pragma unroll
            for (int k = 0; k < 8; k++) s += nv[k]*rwj[r][k];
            f[r] = s;
        }
        #pragma unroll
        for (int r = 0; r < NR; r++)
            #pragma unroll
            for (int off = 16; off; off >>= 1) f[r] += __shfl_xor_sync(0xffffffffu, f[r], off);
        if (lane == 0){
            #pragma unroll
            for (int r = 0; r < NR; r++) atomicAdd(&g_fwd[(b*NR+r)*NN + i], f[r]);
        }
        #pragma unroll
        for (int r = 0; r < NR; r++){
            float rwi = rwi_s[r][ii];
            #pragma unroll
            for (int k = 0; k < 8; k++) bwd[r][k] += rwi*nv[k];
        }
    }
    #pragma unroll
    for (int r = 0; r < NR; r++)
        #pragma unroll
        for (int k = 0; k < 8; k++) atomicAdd(&g_bwd[(b*NR+r)*NN + jb + k], bwd[r][k]);
}

// ---- read content weighting vs mem_new ----
__global__ void k_rcw(const float* __restrict__ out){
    __shared__ float skey[WC];
    __shared__ float logits[NN];
    __shared__ float rbuf[256];
    int b = blockIdx.x >> 2, r = blockIdx.x & 3;
    int tid = threadIdx.x;
    if (tid < WC) skey[tid] = g_readkeys[(b*NR+r)*WC + tid];
    __syncthreads();
    float kn2 = 0.f;
    #pragma unroll
    for (int i = 0; i < WC; i++) kn2 += skey[i]*skey[i];
    float kn = sqrtf(kn2);
    float beta = g_rs[b*NR + r];
    for (int n = tid; n < NN; n += 256){
        const float4* row = (const float4*)(out + OFF_MEM + ((size_t)b*NN + n)*WC);
        float dot = 0.f;
        #pragma unroll
        for (int i = 0; i < WC/4; i++){
            float4 m = row[i];
            dot += m.x*skey[4*i] + m.y*skey[4*i+1] + m.z*skey[4*i+2] + m.w*skey[4*i+3];
        }
        logits[n] = beta*dot/(kn*g_mnorm[b*NN+n] + DELTAF);
    }
    __syncthreads();
    float mx = -1e30f;
    for (int n = tid; n < NN; n += 256) mx = fmaxf(mx, logits[n]);
    rbuf[tid] = mx; __syncthreads();
    for (int s = 128; s; s >>= 1){ if (tid < s) rbuf[tid] = fmaxf(rbuf[tid], rbuf[tid+s]); __syncthreads(); }
    mx = rbuf[0]; __syncthreads();
    float sum = 0.f;
    for (int n = tid; n < NN; n += 256){ float e = expf(logits[n]-mx); logits[n] = e; sum += e; }
    rbuf[tid] = sum; __syncthreads();
    for (int s = 128; s; s >>= 1){ if (tid < s) rbuf[tid] += rbuf[tid+s]; __syncthreads(); }
    float inv = 1.f/rbuf[0];
    for (int n = tid; n < NN; n += 256) g_rcw[(b*NR+r)*NN + n] = logits[n]*inv;
}

// ---- read-mode mix ----
__global__ void k_rw(float* __restrict__ out){
    int b = blockIdx.x >> 2, r = blockIdx.x & 3;
    float m0r = g_rmraw[b*12 + r*3 + 0];
    float m1r = g_rmraw[b*12 + r*3 + 1];
    float m2r = g_rmraw[b*12 + r*3 + 2];
    float mx = fmaxf(m0r, fmaxf(m1r, m2r));
    float e0 = expf(m0r-mx), e1 = expf(m1r-mx), e2 = expf(m2r-mx);
    float inv = 1.f/(e0+e1+e2);
    float mm0 = e0*inv, mm1 = e1*inv, mm2 = e2*inv;
    int base = (b*NR+r)*NN;
    for (int n = threadIdx.x; n < NN; n += 256){
        out[OFF_RW + base + n] = mm0*g_bwd[base+n] + mm1*g_fwd[base+n] + mm2*g_rcw[base+n];
    }
}

// ---- read vectors = rw_new @ mem_new (per batch, smem-tiled) ----
__global__ void k_rv(float* __restrict__ out){
    __shared__ float tile[64*WC];
    __shared__ float srw[NR*64];
    int b = blockIdx.x, tid = threadIdx.x;
    int r = tid >> 6, w = tid & 63;
    float acc = 0.f;
    for (int n0 = 0; n0 < NN; n0 += 64){
        for (int i = tid; i < 64*WC; i += 256)
            tile[i] = out[OFF_MEM + ((size_t)b*NN + n0)*WC + i];
        srw[tid] = out[OFF_RW + (b*NR + r)*NN + n0 + w];
        __syncthreads();
        #pragma unroll 8
        for (int i = 0; i < 64; i++) acc += srw[r*64 + i]*tile[i*WC + w];
        __syncthreads();
    }
    out[OFF_RV + b*256 + tid] = acc;
}

extern "C" void kernel_launch(void* const* d_in, const int* in_sizes, int n_in,
                              void* d_out, int out_size){
    const float* x        = (const float*)d_in[0];
    const float* memory   = (const float*)d_in[1];
    const float* link_old = (const float*)d_in[2];
    const float* prec     = (const float*)d_in[3];
    const float* rw_old   = (const float*)d_in[4];
    const float* ww_old   = (const float*)d_in[5];
    const float* usage0   = (const float*)d_in[6];
    CP cp;
    // seg order: rk, rs, wk, ws, ev, wv, fg, ag, wg, rm
    for (int s = 0; s < 10; s++){
        cp.W[s]    = (const float*)d_in[7 + 2*s];
        cp.bvec[s] = (const float*)d_in[8 + 2*s];
    }
    float* out = (float*)d_out;

    k_zero  <<<256, 256>>>();
    k_ctrl  <<<59, 256>>>(x, cp);
    k_usage <<<(NB*NN + 255)/256, 256>>>(usage0, ww_old, rw_old, out);
    k_wcw   <<<NB, 256>>>(memory);
    k_alloc <<<NB, 1024>>>(out);
    k_ww    <<<NB, 256>>>(prec, out);
    k_memnew<<<NB*NN/8, 256>>>(memory, out);
    k_link  <<<dim3(NN/TI, NB), 256>>>(link_old, prec, rw_old, out);
    k_rcw   <<<NB*NR, 256>>>(out);
    k_rw    <<<NB*NR, 256>>>(out);
    k_rv    <<<NB, 256>>>(out);
}

// round 2
// speedup vs baseline: 1.6481x; 1.6481x over previous
#include <cuda_runtime.h>
#include <math.h>

#define NB 16
#define NN 2048
#define WC 64
#define NR 4
#define NI 512
#define DELTAF 1e-6f
#define TI 64

// ---- output offsets (flattened tuple order) ----
#define OFF_RV    0
#define OFF_MEM   (NB*NR*WC)                 // 4096
#define OFF_LINK  (OFF_MEM + NB*NN*WC)       // 2101248
#define OFF_PREC  (OFF_LINK + NB*NN*NN)      // 69210112
#define OFF_RW    (OFF_PREC + NB*NN)         // 69242880
#define OFF_WW    (OFF_RW + NB*NR*NN)        // 69373952
#define OFF_USAGE (OFF_WW + NB*NN)           // 69406720

// ---- device scratch ----
__device__ float g_readkeys[NB*NR*WC];
__device__ float g_rs[NB*NR];
__device__ float g_wkey[NB*WC];
__device__ float g_wstr[NB];
__device__ float g_ev[NB*WC];
__device__ float g_wv[NB*WC];
__device__ float g_fg[NB*NR];
__device__ float g_ag[NB];
__device__ float g_wg[NB];
__device__ float g_rmraw[NB*12];
__device__ float g_wcwlog[NB*NN];   // write-content logits (softmax fused into k_ww)
__device__ float g_alloc[NB*NN];
__device__ float g_fwd[NB*NR*NN];   // written directly (no atomics)
__device__ float g_bwd[NB*NR*NN];   // atomic accumulated
__device__ float g_rcw[NB*NR*NN];   // logits in place, softmaxed in place

struct CP { const float* W[10]; const float* bvec[10]; };

__device__ __forceinline__ float act_apply(int code, float v){
    switch(code){
        case 0: return tanhf(v);
        case 1: return fmaxf(v, 0.f) + log1pf(expf(-fabsf(v)));  // softplus
        case 2: return 1.f/(1.f + expf(-v));                      // sigmoid
        default: return v;
    }
}

__device__ __forceinline__ float* seg_out(int seg){
    switch(seg){
        case 0: return g_readkeys;
        case 1: return g_rs;
        case 2: return g_wkey;
        case 3: return g_wstr;
        case 4: return g_ev;
        case 5: return g_wv;
        case 6: return g_fg;
        case 7: return g_ag;
        case 8: return g_wg;
        default: return g_rmraw;
    }
}

// ---- zero bwd accumulator + read-vector output region ----
__global__ void k_zero(float* __restrict__ out){
    int id = blockIdx.x*blockDim.x + threadIdx.x;
    if (id < NB*NR*NN) g_bwd[id] = 0.f;
    else if (id < NB*NR*NN + NB*NR*WC) out[OFF_RV + id - NB*NR*NN] = 0.f;
}

// ---- controller projections: one warp per output row (471 rows) ----
__global__ void k_ctrl(const float* __restrict__ x, CP cp){
    __shared__ float sx[NB*NI];
    int tid = threadIdx.x;
    for (int i = tid; i < NB*NI; i += blockDim.x) sx[i] = x[i];
    __syncthreads();
    int gw = (blockIdx.x*blockDim.x + tid) >> 5;
    int lane = tid & 31;
    if (gw >= 471) return;
    const int segStart[10] = {0,256,260,324,325,389,453,457,458,459};
    const int segLen[10]   = {256,4,64,1,64,64,4,1,1,12};
    const int segAct[10]   = {0,1,0,1,2,0,2,2,2,3};
    int seg = 0;
    for (int s = 9; s >= 0; s--){ if (gw >= segStart[s]){ seg = s; break; } }
    int rl = gw - segStart[seg];
    const float* W = cp.W[seg] + rl*NI;
    float wreg[16];
    #pragma unroll
    for (int s = 0; s < 16; s++) wreg[s] = W[s*32 + lane];
    float bias = cp.bvec[seg][rl];
    float* outp = seg_out(seg);
    int sl = segLen[seg], ac = segAct[seg];
    for (int b = 0; b < NB; b++){
        const float* xb = &sx[b*NI];
        float sum = 0.f;
        #pragma unroll
        for (int s = 0; s < 16; s++) sum += wreg[s]*xb[s*32 + lane];
        #pragma unroll
        for (int off = 16; off; off >>= 1) sum += __shfl_xor_sync(0xffffffffu, sum, off);
        if (lane == 0) outp[b*sl + rl] = act_apply(ac, sum + bias);
    }
}

// ---- write-content logits: 128 blocks, one n per thread ----
__global__ void k_wcwlog(const float* __restrict__ mem){
    __shared__ float skey[WC];
    int b = blockIdx.x >> 3;
    int c = blockIdx.x & 7;
    int tid = threadIdx.x;
    if (tid < WC) skey[tid] = g_wkey[b*WC + tid];
    __syncthreads();
    float kn2 = 0.f;
    #pragma unroll
    for (int i = 0; i < WC; i++) kn2 += skey[i]*skey[i];
    float kn = sqrtf(kn2);
    float beta = g_wstr[b];
    int n = c*256 + tid;
    const float4* row = (const float4*)(mem + ((size_t)b*NN + n)*WC);
    float dot = 0.f, sq = 0.f;
    #pragma unroll
    for (int i = 0; i < WC/4; i++){
        float4 m = row[i];
        dot += m.x*skey[4*i] + m.y*skey[4*i+1] + m.z*skey[4*i+2] + m.w*skey[4*i+3];
        sq  += m.x*m.x + m.y*m.y + m.z*m.z + m.w*m.w;
    }
    g_wcwlog[b*NN + n] = beta*dot/(kn*sqrtf(sq) + DELTAF);
}

// ---- usage + allocation weighting (bitonic sort + shuffle scan), per batch ----
__global__ void __launch_bounds__(1024)
k_alloc(const float* __restrict__ u0v, const float* __restrict__ wwold,
        const float* __restrict__ rwold, float* __restrict__ out){
    __shared__ unsigned long long keys[NN];
    __shared__ float warptot[32];
    __shared__ float warpoff[32];
    int b = blockIdx.x, tid = threadIdx.x;   // 1024 threads
    int lane = tid & 31, wid = tid >> 5;
    for (int i = tid; i < NN; i += 1024){
        float u0 = u0v[b*NN + i];
        float u = u0 + (1.f - u0)*wwold[b*NN + i];
        float ret = 1.f;
        #pragma unroll
        for (int r = 0; r < NR; r++) ret *= (1.f - g_fg[b*NR+r]*rwold[(b*NR+r)*NN + i]);
        float usage = u*ret;
        out[OFF_USAGE + b*NN + i] = usage;
        float uu = DELTAF + (1.f - DELTAF)*usage;
        keys[i] = ((unsigned long long)__float_as_uint(uu) << 32) | (unsigned)i;
    }
    __syncthreads();
    for (int k = 2; k <= NN; k <<= 1){
        for (int j = k >> 1; j > 0; j >>= 1){
            for (int i = tid; i < NN; i += 1024){
                int ixj = i ^ j;
                if (ixj > i){
                    bool up = ((i & k) == 0);
                    unsigned long long a = keys[i], c = keys[ixj];
                    if (up ? (a > c) : (a < c)){ keys[i] = c; keys[ixj] = a; }
                }
            }
            if (j >= 32) __syncthreads(); else __syncwarp();
        }
        if (k >= 32) __syncthreads();
    }
    __syncthreads();
    // exclusive prefix product over sorted u via shuffle scan (2 elems/thread)
    unsigned long long k0 = keys[2*tid], k1 = keys[2*tid + 1];
    float u0s = __uint_as_float((unsigned)(k0 >> 32));
    float u1s = __uint_as_float((unsigned)(k1 >> 32));
    float p = u0s*u1s;
    float incl = p;
    #pragma unroll
    for (int d = 1; d < 32; d <<= 1){
        float v = __shfl_up_sync(0xffffffffu, incl, d);
        if (lane >= d) incl *= v;
    }
    if (lane == 31) warptot[wid] = incl;
    __syncthreads();
    if (wid == 0){
        float wv = warptot[lane];
        float winc = wv;
        #pragma unroll
        for (int d = 1; d < 32; d <<= 1){
            float v = __shfl_up_sync(0xffffffffu, winc, d);
            if (lane >= d) winc *= v;
        }
        float wex = __shfl_up_sync(0xffffffffu, winc, 1);
        if (lane == 0) wex = 1.f;
        warpoff[lane] = wex;
    }
    __syncthreads();
    float excl = __shfl_up_sync(0xffffffffu, incl, 1);
    if (lane == 0) excl = 1.f;
    float pre0 = warpoff[wid]*excl;     // product of all sorted u before element 2*tid
    float pre1 = pre0*u0s;
    int o0 = (int)(k0 & 0xffffffffu);
    int o1 = (int)(k1 & 0xffffffffu);
    g_alloc[b*NN + o0] = (1.f - u0s)*pre0;
    g_alloc[b*NN + o1] = (1.f - u1s)*pre1;
}

// ---- wcw softmax + ww + precedence (per batch) ----
__global__ void k_ww(const float* __restrict__ prec_old, float* __restrict__ out){
    __shared__ float sl[NN];
    __shared__ float rbuf[256];
    int b = blockIdx.x, tid = threadIdx.x;
    float mx = -1e30f;
    #pragma unroll
    for (int k = 0; k < 8; k++){
        float v = g_wcwlog[b*NN + k*256 + tid];
        sl[k*256 + tid] = v;
        mx = fmaxf(mx, v);
    }
    rbuf[tid] = mx; __syncthreads();
    for (int s = 128; s; s >>= 1){ if (tid < s) rbuf[tid] = fmaxf(rbuf[tid], rbuf[tid+s]); __syncthreads(); }
    mx = rbuf[0]; __syncthreads();
    float sum = 0.f;
    #pragma unroll
    for (int k = 0; k < 8; k++){
        float e = expf(sl[k*256 + tid] - mx);
        sl[k*256 + tid] = e; sum += e;
    }
    rbuf[tid] = sum; __syncthreads();
    for (int s = 128; s; s >>= 1){ if (tid < s) rbuf[tid] += rbuf[tid+s]; __syncthreads(); }
    float inv = 1.f/rbuf[0];
    __syncthreads();
    float agv = g_ag[b], wgv = g_wg[b];
    float wwv[8], s2 = 0.f;
    #pragma unroll
    for (int k = 0; k < 8; k++){
        int n = k*256 + tid;
        float w = wgv*(agv*g_alloc[b*NN+n] + (1.f-agv)*sl[n]*inv);
        wwv[k] = w; s2 += w;
        out[OFF_WW + b*NN + n] = w;
    }
    rbuf[tid] = s2; __syncthreads();
    for (int st = 128; st; st >>= 1){ if (tid < st) rbuf[tid] += rbuf[tid+st]; __syncthreads(); }
    float S = rbuf[0];
    #pragma unroll
    for (int k = 0; k < 8; k++){
        int n = k*256 + tid;
        out[OFF_PREC + b*NN + n] = (1.f - S)*prec_old[b*NN + n] + wwv[k];
    }
}

// ---- memory update + read-content logits (fused), one warp per row ----
__global__ void k_memnew(const float* __restrict__ mem, float* __restrict__ out){
    __shared__ float skey[NR*WC];
    __shared__ float sknorm[NR];
    __shared__ float sev[WC], swv[WC];
    int b = blockIdx.x >> 8;
    int rowblk = blockIdx.x & 255;
    int tid = threadIdx.x;
    skey[tid] = g_readkeys[b*NR*WC + tid];
    if (tid < WC){ sev[tid] = g_ev[b*WC + tid]; swv[tid] = g_wv[b*WC + tid]; }
    __syncthreads();
    if (tid < NR){
        float s = 0.f;
        #pragma unroll
        for (int i = 0; i < WC; i++){ float v = skey[tid*WC + i]; s += v*v; }
        sknorm[tid] = sqrtf(s);
    }
    __syncthreads();
    int wrp = tid >> 5, lane = tid & 31;
    int n = rowblk*8 + wrp;
    int row = b*NN + n;
    int w0 = lane*2;
    float2 m = *(const float2*)(mem + (size_t)row*WC + w0);
    float ww = out[OFF_WW + row];
    float n0 = m.x*(1.f - ww*sev[w0])   + ww*swv[w0];
    float n1 = m.y*(1.f - ww*sev[w0+1]) + ww*swv[w0+1];
    *(float2*)(out + OFF_MEM + (size_t)row*WC + w0) = make_float2(n0, n1);
    float d[NR], sq = n0*n0 + n1*n1;
    #pragma unroll
    for (int r = 0; r < NR; r++) d[r] = n0*skey[r*WC + w0] + n1*skey[r*WC + w0 + 1];
    #pragma unroll
    for (int off = 16; off; off >>= 1){
        sq += __shfl_xor_sync(0xffffffffu, sq, off);
        #pragma unroll
        for (int r = 0; r < NR; r++) d[r] += __shfl_xor_sync(0xffffffffu, d[r], off);
    }
    if (lane == 0){
        float mn = sqrtf(sq);
        #pragma unroll
        for (int r = 0; r < NR; r++)
            g_rcw[(b*NR+r)*NN + n] = g_rs[b*NR+r]*d[r]/(sknorm[r]*mn + DELTAF);
    }
}

// ---- read-content softmax (in place), one block per (b,r) ----
__global__ void k_rcwsm(){
    __shared__ float sl[NN];
    __shared__ float rbuf[256];
    int base = blockIdx.x*NN;
    int tid = threadIdx.x;
    float mx = -1e30f;
    #pragma unroll
    for (int k = 0; k < 8; k++){
        float v = g_rcw[base + k*256 + tid];
        sl[k*256 + tid] = v;
        mx = fmaxf(mx, v);
    }
    rbuf[tid] = mx; __syncthreads();
    for (int s = 128; s; s >>= 1){ if (tid < s) rbuf[tid] = fmaxf(rbuf[tid], rbuf[tid+s]); __syncthreads(); }
    mx = rbuf[0]; __syncthreads();
    float sum = 0.f;
    #pragma unroll
    for (int k = 0; k < 8; k++){
        float e = expf(sl[k*256 + tid] - mx);
        sl[k*256 + tid] = e; sum += e;
    }
    rbuf[tid] = sum; __syncthreads();
    for (int s = 128; s; s >>= 1){ if (tid < s) rbuf[tid] += rbuf[tid+s]; __syncthreads(); }
    float inv = 1.f/rbuf[0];
    #pragma unroll
    for (int k = 0; k < 8; k++) g_rcw[base + k*256 + tid] = sl[k*256 + tid]*inv;
}

// ---- fused link update + fwd/bwd einsums (single pass over L) ----
__global__ void __launch_bounds__(256, 2)
k_link(const float* __restrict__ link_old, const float* __restrict__ prec_old,
       const float* __restrict__ rw_old, float* __restrict__ out){
    __shared__ float wwi_s[TI];
    __shared__ float rwi_s[NR][TI];
    __shared__ float sfwd[TI][NR][8];
    int b = blockIdx.y;
    int i0 = blockIdx.x * TI;
    int tid = threadIdx.x;
    int wrp = tid >> 5, lane = tid & 31;
    if (tid < TI) wwi_s[tid] = out[OFF_WW + b*NN + i0 + tid];
    {
        int r = tid >> 6, ii = tid & 63;   // 256 threads = 4*64
        rwi_s[r][ii] = rw_old[(b*NR+r)*NN + i0 + ii];
    }
    int jb = tid * 8;
    float wwj[8], pj[8], rwj[NR][8];
    #pragma unroll
    for (int k = 0; k < 8; k++){
        wwj[k] = out[OFF_WW + b*NN + jb + k];
        pj[k]  = prec_old[b*NN + jb + k];
    }
    #pragma unroll
    for (int r = 0; r < NR; r++)
        #pragma unroll
        for (int k = 0; k < 8; k++) rwj[r][k] = rw_old[(b*NR+r)*NN + jb + k];
    float bwd[NR][8];
    #pragma unroll
    for (int r = 0; r < NR; r++)
        #pragma unroll
        for (int k = 0; k < 8; k++) bwd[r][k] = 0.f;
    __syncthreads();
    const float* Lb = link_old + ((size_t)b*NN + i0)*NN + jb;
    float* Ob = out + OFF_LINK + ((size_t)b*NN + i0)*NN + jb;
    #pragma unroll 4
    for (int ii = 0; ii < TI; ii++){
        int i = i0 + ii;
        float wwi = wwi_s[ii];
        const float4* L4 = (const float4*)(Lb + (size_t)ii*NN);
        float4 o0 = L4[0], o1 = L4[1];
        float old[8] = {o0.x,o0.y,o0.z,o0.w,o1.x,o1.y,o1.z,o1.w};
        float nv[8];
        #pragma unroll
        for (int k = 0; k < 8; k++){
            float v = (1.f - wwi - wwj[k])*old[k] + wwi*pj[k];
            if (jb + k == i) v = 0.f;
            nv[k] = v;
        }
        float4* O4 = (float4*)(Ob + (size_t)ii*NN);
        O4[0] = make_float4(nv[0],nv[1],nv[2],nv[3]);
        O4[1] = make_float4(nv[4],nv[5],nv[6],nv[7]);
        float f[NR];
        #pragma unroll
        for (int r = 0; r < NR; r++){
            float s = 0.f;
            #pragma unroll
            for (int k = 0; k < 8; k++) s += nv[k]*rwj[r][k];
            f[r] = s;
        }
        #pragma unroll
        for (int off = 16; off; off >>= 1)
            #pragma unroll
            for (int r = 0; r < NR; r++) f[r] += __shfl_xor_sync(0xffffffffu, f[r], off);
        if (lane == 0){
            #pragma unroll
            for (int r = 0; r < NR; r++) sfwd[ii][r][wrp] = f[r];
        }
        #pragma unroll
        for (int r = 0; r < NR; r++){
            float rwi = rwi_s[r][ii];
            #pragma unroll
            for (int k = 0; k < 8; k++) bwd[r][k] += rwi*nv[k];
        }
    }
    __syncthreads();
    {   // fwd: reduce 8 warps, direct store (this block owns these i)
        int ii = tid >> 2, r = tid & 3;   // 256 = 64*4
        float s = 0.f;
        #pragma unroll
        for (int w = 0; w < 8; w++) s += sfwd[ii][r][w];
        g_fwd[(b*NR+r)*NN + i0 + ii] = s;
    }
    #pragma unroll
    for (int r = 0; r < NR; r++)
        #pragma unroll
        for (int k = 0; k < 8; k++) atomicAdd(&g_bwd[(b*NR+r)*NN + jb + k], bwd[r][k]);
}

// ---- rw_new mix + read vectors (partial over 64-n chunks, atomics into out) ----
__global__ void k_rvrw(float* __restrict__ out){
    __shared__ float tile[64*WC];
    __shared__ float srw[NR*64];
    int b = blockIdx.x >> 5;
    int c = blockIdx.x & 31;
    int tid = threadIdx.x;
    int r = tid >> 6, idx = tid & 63;
    int n0 = c*64, n = n0 + idx;
    float m0r = g_rmraw[b*12 + r*3 + 0];
    float m1r = g_rmraw[b*12 + r*3 + 1];
    float m2r = g_rmraw[b*12 + r*3 + 2];
    float mx = fmaxf(m0r, fmaxf(m1r, m2r));
    float e0 = expf(m0r-mx), e1 = expf(m1r-mx), e2 = expf(m2r-mx);
    float inv = 1.f/(e0+e1+e2);
    int base = (b*NR+r)*NN;
    float rwv = e0*inv*g_bwd[base+n] + e1*inv*g_fwd[base+n] + e2*inv*g_rcw[base+n];
    out[OFF_RW + base + n] = rwv;
    srw[r*64 + idx] = rwv;
    for (int i = tid; i < 64*WC; i += 256)
        tile[i] = out[OFF_MEM + ((size_t)b*NN + n0)*WC + i];
    __syncthreads();
    float acc = 0.f;
    #pragma unroll 8
    for (int i = 0; i < 64; i++) acc += srw[r*64 + i]*tile[i*WC + idx];
    atomicAdd(&out[OFF_RV + b*256 + r*64 + idx], acc);
}

extern "C" void kernel_launch(void* const* d_in, const int* in_sizes, int n_in,
                              void* d_out, int out_size){
    const float* x        = (const float*)d_in[0];
    const float* memory   = (const float*)d_in[1];
    const float* link_old = (const float*)d_in[2];
    const float* prec     = (const float*)d_in[3];
    const float* rw_old   = (const float*)d_in[4];
    const float* ww_old   = (const float*)d_in[5];
    const float* usage0   = (const float*)d_in[6];
    CP cp;
    for (int s = 0; s < 10; s++){
        cp.W[s]    = (const float*)d_in[7 + 2*s];
        cp.bvec[s] = (const float*)d_in[8 + 2*s];
    }
    float* out = (float*)d_out;

    k_zero  <<<(NB*NR*NN + NB*NR*WC + 255)/256, 256>>>(out);
    k_ctrl  <<<59, 256>>>(x, cp);
    k_wcwlog<<<NB*8, 256>>>(memory);
    k_alloc <<<NB, 1024>>>(usage0, ww_old, rw_old, out);
    k_ww    <<<NB, 256>>>(prec, out);
    k_memnew<<<NB*256, 256>>>(memory, out);
    k_rcwsm <<<NB*NR, 256>>>();
    k_link  <<<dim3(NN/TI, NB), 256>>>(link_old, prec, rw_old, out);
    k_rvrw  <<<NB*32, 256>>>(out);
}

// round 3
// speedup vs baseline: 1.8798x; 1.1406x over previous
#include <cuda_runtime.h>
#include <math.h>

#define NB 16
#define NN 2048
#define WC 64
#define NR 4
#define NI 512
#define DELTAF 1e-6f
#define TI 64

// ---- output offsets (flattened tuple order) ----
#define OFF_RV    0
#define OFF_MEM   (NB*NR*WC)                 // 4096
#define OFF_LINK  (OFF_MEM + NB*NN*WC)       // 2101248
#define OFF_PREC  (OFF_LINK + NB*NN*NN)      // 69210112
#define OFF_RW    (OFF_PREC + NB*NN)         // 69242880
#define OFF_WW    (OFF_RW + NB*NR*NN)        // 69373952
#define OFF_USAGE (OFF_WW + NB*NN)           // 69406720

// ---- device scratch ----
__device__ float g_readkeys[NB*NR*WC];
__device__ float g_rs[NB*NR];
__device__ float g_wkey[NB*WC];
__device__ float g_wstr[NB];
__device__ float g_ev[NB*WC];
__device__ float g_wv[NB*WC];
__device__ float g_fg[NB*NR];
__device__ float g_ag[NB];
__device__ float g_wg[NB];
__device__ float g_rmraw[NB*12];
__device__ float g_wcwlog[NB*NN];
__device__ float g_alloc[NB*NN];
__device__ float g_fwd[NB*NR*NN];   // direct stores
__device__ float g_bwd[NB*NR*NN];   // atomic accumulated
__device__ float g_rcw[NB*NR*NN];   // logits -> softmaxed in place

struct CP { const float* W[10]; const float* bvec[10]; };

__device__ __forceinline__ float act_apply(int code, float v){
    switch(code){
        case 0: return tanhf(v);
        case 1: return fmaxf(v, 0.f) + log1pf(expf(-fabsf(v)));  // softplus
        case 2: return 1.f/(1.f + expf(-v));                      // sigmoid
        default: return v;
    }
}

__device__ __forceinline__ float* seg_out(int seg){
    switch(seg){
        case 0: return g_readkeys;
        case 1: return g_rs;
        case 2: return g_wkey;
        case 3: return g_wstr;
        case 4: return g_ev;
        case 5: return g_wv;
        case 6: return g_fg;
        case 7: return g_ag;
        case 8: return g_wg;
        default: return g_rmraw;
    }
}

// ---- zero bwd accumulator + read-vector output region ----
__global__ void k_zero(float* __restrict__ out){
    int id = blockIdx.x*blockDim.x + threadIdx.x;
    if (id < NB*NR*NN) g_bwd[id] = 0.f;
    else if (id < NB*NR*NN + NB*NR*WC) out[OFF_RV + id - NB*NR*NN] = 0.f;
}

// ---- controller projections: one warp per output row (471 rows) ----
__global__ void k_ctrl(const float* __restrict__ x, CP cp){
    __shared__ float sx[NB*NI];
    int tid = threadIdx.x;
    for (int i = tid; i < NB*NI; i += blockDim.x) sx[i] = x[i];
    __syncthreads();
    int gw = (blockIdx.x*blockDim.x + tid) >> 5;
    int lane = tid & 31;
    if (gw >= 471) return;
    const int segStart[10] = {0,256,260,324,325,389,453,457,458,459};
    const int segLen[10]   = {256,4,64,1,64,64,4,1,1,12};
    const int segAct[10]   = {0,1,0,1,2,0,2,2,2,3};
    int seg = 0;
    for (int s = 9; s >= 0; s--){ if (gw >= segStart[s]){ seg = s; break; } }
    int rl = gw - segStart[seg];
    const float* W = cp.W[seg] + rl*NI;
    float wreg[16];
    #pragma unroll
    for (int s = 0; s < 16; s++) wreg[s] = W[s*32 + lane];
    float bias = cp.bvec[seg][rl];
    float* outp = seg_out(seg);
    int sl = segLen[seg], ac = segAct[seg];
    for (int b = 0; b < NB; b++){
        const float* xb = &sx[b*NI];
        float sum = 0.f;
        #pragma unroll
        for (int s = 0; s < 16; s++) sum += wreg[s]*xb[s*32 + lane];
        #pragma unroll
        for (int off = 16; off; off >>= 1) sum += __shfl_xor_sync(0xffffffffu, sum, off);
        if (lane == 0) outp[b*sl + rl] = act_apply(ac, sum + bias);
    }
}

// ---- write-content logits: 128 blocks, one n per thread ----
__global__ void k_wcwlog(const float* __restrict__ mem){
    __shared__ float skey[WC];
    int b = blockIdx.x >> 3;
    int c = blockIdx.x & 7;
    int tid = threadIdx.x;
    if (tid < WC) skey[tid] = g_wkey[b*WC + tid];
    __syncthreads();
    float kn2 = 0.f;
    #pragma unroll
    for (int i = 0; i < WC; i++) kn2 += skey[i]*skey[i];
    float kn = sqrtf(kn2);
    float beta = g_wstr[b];
    int n = c*256 + tid;
    const float4* row = (const float4*)(mem + ((size_t)b*NN + n)*WC);
    float dot = 0.f, sq = 0.f;
    #pragma unroll
    for (int i = 0; i < WC/4; i++){
        float4 m = row[i];
        dot += m.x*skey[4*i] + m.y*skey[4*i+1] + m.z*skey[4*i+2] + m.w*skey[4*i+3];
        sq  += m.x*m.x + m.y*m.y + m.z*m.z + m.w*m.w;
    }
    g_wcwlog[b*NN + n] = beta*dot/(kn*sqrtf(sq) + DELTAF);
}

// ---- usage + allocation weighting: 32-bit-key bitonic sort + shuffle scan ----
__global__ void __launch_bounds__(1024)
k_alloc(const float* __restrict__ u0v, const float* __restrict__ wwold,
        const float* __restrict__ rwold, float* __restrict__ out){
    __shared__ unsigned keys[NN];
    __shared__ float su[NN];
    __shared__ float warptot[32];
    __shared__ float warpoff[32];
    int b = blockIdx.x, tid = threadIdx.x;   // 1024 threads
    int lane = tid & 31, wid = tid >> 5;
    for (int i = tid; i < NN; i += 1024){
        float u0 = u0v[b*NN + i];
        float u = u0 + (1.f - u0)*wwold[b*NN + i];
        float ret = 1.f;
        #pragma unroll
        for (int r = 0; r < NR; r++) ret *= (1.f - g_fg[b*NR+r]*rwold[(b*NR+r)*NN + i]);
        float usage = u*ret;
        out[OFF_USAGE + b*NN + i] = usage;
        float uu = DELTAF + (1.f - DELTAF)*usage;
        su[i] = uu;
        keys[i] = (__float_as_uint(uu) & 0xFFFFF800u) | (unsigned)i;
    }
    __syncthreads();
    for (int k = 2; k <= NN; k <<= 1){
        for (int j = k >> 1; j > 0; j >>= 1){
            #pragma unroll
            for (int h = 0; h < 2; h++){
                int i = h*1024 + tid;
                int ixj = i ^ j;
                if (ixj > i){
                    bool up = ((i & k) == 0);
                    unsigned a = keys[i], c = keys[ixj];
                    if (up ? (a > c) : (a < c)){ keys[i] = c; keys[ixj] = a; }
                }
            }
            if (j >= 32) __syncthreads(); else __syncwarp();
        }
        if (k >= 32) __syncthreads();
    }
    __syncthreads();
    // exclusive prefix product over sorted exact u (2 elems/thread)
    unsigned k0 = keys[2*tid], k1 = keys[2*tid + 1];
    float u0s = su[k0 & 0x7FFu];
    float u1s = su[k1 & 0x7FFu];
    float incl = u0s*u1s;
    #pragma unroll
    for (int d = 1; d < 32; d <<= 1){
        float v = __shfl_up_sync(0xffffffffu, incl, d);
        if (lane >= d) incl *= v;
    }
    if (lane == 31) warptot[wid] = incl;
    __syncthreads();
    if (wid == 0){
        float winc = warptot[lane];
        #pragma unroll
        for (int d = 1; d < 32; d <<= 1){
            float v = __shfl_up_sync(0xffffffffu, winc, d);
            if (lane >= d) winc *= v;
        }
        float wex = __shfl_up_sync(0xffffffffu, winc, 1);
        if (lane == 0) wex = 1.f;
        warpoff[lane] = wex;
    }
    __syncthreads();
    float excl = __shfl_up_sync(0xffffffffu, incl, 1);
    if (lane == 0) excl = 1.f;
    float pre0 = warpoff[wid]*excl;
    float pre1 = pre0*u0s;
    g_alloc[b*NN + (k0 & 0x7FFu)] = (1.f - u0s)*pre0;
    g_alloc[b*NN + (k1 & 0x7FFu)] = (1.f - u1s)*pre1;
}

// ---- wcw softmax + ww + precedence (per batch) ----
__global__ void k_ww(const float* __restrict__ prec_old, float* __restrict__ out){
    __shared__ float sl[NN];
    __shared__ float rbuf[256];
    int b = blockIdx.x, tid = threadIdx.x;
    float mx = -1e30f;
    #pragma unroll
    for (int k = 0; k < 8; k++){
        float v = g_wcwlog[b*NN + k*256 + tid];
        sl[k*256 + tid] = v;
        mx = fmaxf(mx, v);
    }
    rbuf[tid] = mx; __syncthreads();
    for (int s = 128; s; s >>= 1){ if (tid < s) rbuf[tid] = fmaxf(rbuf[tid], rbuf[tid+s]); __syncthreads(); }
    mx = rbuf[0]; __syncthreads();
    float sum = 0.f;
    #pragma unroll
    for (int k = 0; k < 8; k++){
        float e = expf(sl[k*256 + tid] - mx);
        sl[k*256 + tid] = e; sum += e;
    }
    rbuf[tid] = sum; __syncthreads();
    for (int s = 128; s; s >>= 1){ if (tid < s) rbuf[tid] += rbuf[tid+s]; __syncthreads(); }
    float inv = 1.f/rbuf[0];
    __syncthreads();
    float agv = g_ag[b], wgv = g_wg[b];
    float wwv[8], s2 = 0.f;
    #pragma unroll
    for (int k = 0; k < 8; k++){
        int n = k*256 + tid;
        float w = wgv*(agv*g_alloc[b*NN+n] + (1.f-agv)*sl[n]*inv);
        wwv[k] = w; s2 += w;
        out[OFF_WW + b*NN + n] = w;
    }
    rbuf[tid] = s2; __syncthreads();
    for (int st = 128; st; st >>= 1){ if (tid < st) rbuf[tid] += rbuf[tid+st]; __syncthreads(); }
    float S = rbuf[0];
    #pragma unroll
    for (int k = 0; k < 8; k++){
        int n = k*256 + tid;
        out[OFF_PREC + b*NN + n] = (1.f - S)*prec_old[b*NN + n] + wwv[k];
    }
}

// ---- memory update + read-content logits (fused), one warp per row ----
__global__ void k_memnew(const float* __restrict__ mem, float* __restrict__ out){
    __shared__ float skey[NR*WC];
    __shared__ float sknorm[NR];
    __shared__ float sev[WC], swv[WC];
    int b = blockIdx.x >> 8;
    int rowblk = blockIdx.x & 255;
    int tid = threadIdx.x;
    skey[tid] = g_readkeys[b*NR*WC + tid];
    if (tid < WC){ sev[tid] = g_ev[b*WC + tid]; swv[tid] = g_wv[b*WC + tid]; }
    __syncthreads();
    if (tid < NR){
        float s = 0.f;
        #pragma unroll
        for (int i = 0; i < WC; i++){ float v = skey[tid*WC + i]; s += v*v; }
        sknorm[tid] = sqrtf(s);
    }
    __syncthreads();
    int wrp = tid >> 5, lane = tid & 31;
    int n = rowblk*8 + wrp;
    int row = b*NN + n;
    int w0 = lane*2;
    float2 m = *(const float2*)(mem + (size_t)row*WC + w0);
    float ww = out[OFF_WW + row];
    float n0 = m.x*(1.f - ww*sev[w0])   + ww*swv[w0];
    float n1 = m.y*(1.f - ww*sev[w0+1]) + ww*swv[w0+1];
    *(float2*)(out + OFF_MEM + (size_t)row*WC + w0) = make_float2(n0, n1);
    float d[NR], sq = n0*n0 + n1*n1;
    #pragma unroll
    for (int r = 0; r < NR; r++) d[r] = n0*skey[r*WC + w0] + n1*skey[r*WC + w0 + 1];
    #pragma unroll
    for (int off = 16; off; off >>= 1){
        sq += __shfl_xor_sync(0xffffffffu, sq, off);
        #pragma unroll
        for (int r = 0; r < NR; r++) d[r] += __shfl_xor_sync(0xffffffffu, d[r], off);
    }
    if (lane == 0){
        float mn = sqrtf(sq);
        #pragma unroll
        for (int r = 0; r < NR; r++)
            g_rcw[(b*NR+r)*NN + n] = g_rs[b*NR+r]*d[r]/(sknorm[r]*mn + DELTAF);
    }
}

// ---- read-content softmax (in place), one block per (b,r) ----
__global__ void k_rcwsm(){
    __shared__ float sl[NN];
    __shared__ float rbuf[256];
    int base = blockIdx.x*NN;
    int tid = threadIdx.x;
    float mx = -1e30f;
    #pragma unroll
    for (int k = 0; k < 8; k++){
        float v = g_rcw[base + k*256 + tid];
        sl[k*256 + tid] = v;
        mx = fmaxf(mx, v);
    }
    rbuf[tid] = mx; __syncthreads();
    for (int s = 128; s; s >>= 1){ if (tid < s) rbuf[tid] = fmaxf(rbuf[tid], rbuf[tid+s]); __syncthreads(); }
    mx = rbuf[0]; __syncthreads();
    float sum = 0.f;
    #pragma unroll
    for (int k = 0; k < 8; k++){
        float e = expf(sl[k*256 + tid] - mx);
        sl[k*256 + tid] = e; sum += e;
    }
    rbuf[tid] = sum; __syncthreads();
    for (int s = 128; s; s >>= 1){ if (tid < s) rbuf[tid] += rbuf[tid+s]; __syncthreads(); }
    float inv = 1.f/rbuf[0];
    #pragma unroll
    for (int k = 0; k < 8; k++) g_rcw[base + k*256 + tid] = sl[k*256 + tid]*inv;
}

// ---- fused link update + fwd/bwd einsums (single pass over L) ----
__global__ void __launch_bounds__(256, 2)
k_link(const float* __restrict__ link_old, const float* __restrict__ prec_old,
       const float* __restrict__ rw_old, float* __restrict__ out){
    __shared__ float wwi_s[TI];
    __shared__ float rwi_s[NR][TI];
    __shared__ float sfwd[TI][NR][33];   // padded: conflict-free final reduce
    int b = blockIdx.y;
    int i0 = blockIdx.x * TI;
    int tid = threadIdx.x;
    int wrp = tid >> 5, lane = tid & 31;
    if (tid < TI) wwi_s[tid] = out[OFF_WW + b*NN + i0 + tid];
    {
        int r = tid >> 6, ii = tid & 63;
        rwi_s[r][ii] = rw_old[(b*NR+r)*NN + i0 + ii];
    }
    int jb = tid * 8;
    float wwj[8], pj[8], rwj[NR][8];
    #pragma unroll
    for (int k = 0; k < 8; k++){
        wwj[k] = out[OFF_WW + b*NN + jb + k];
        pj[k]  = prec_old[b*NN + jb + k];
    }
    #pragma unroll
    for (int r = 0; r < NR; r++)
        #pragma unroll
        for (int k = 0; k < 8; k++) rwj[r][k] = rw_old[(b*NR+r)*NN + jb + k];
    float bwd[NR][8];
    #pragma unroll
    for (int r = 0; r < NR; r++)
        #pragma unroll
        for (int k = 0; k < 8; k++) bwd[r][k] = 0.f;
    __syncthreads();
    const float* Lb = link_old + ((size_t)b*NN + i0)*NN + jb;
    float* Ob = out + OFF_LINK + ((size_t)b*NN + i0)*NN + jb;
    int slot = wrp*4 + (lane >> 3);
    #pragma unroll 4
    for (int ii = 0; ii < TI; ii++){
        int i = i0 + ii;
        float wwi = wwi_s[ii];
        const float4* L4 = (const float4*)(Lb + (size_t)ii*NN);
        float4 o0 = __ldcs(L4);
        float4 o1 = __ldcs(L4 + 1);
        float old[8] = {o0.x,o0.y,o0.z,o0.w,o1.x,o1.y,o1.z,o1.w};
        float nv[8];
        #pragma unroll
        for (int k = 0; k < 8; k++){
            float v = (1.f - wwi - wwj[k])*old[k] + wwi*pj[k];
            if (jb + k == i) v = 0.f;
            nv[k] = v;
        }
        float4* O4 = (float4*)(Ob + (size_t)ii*NN);
        __stcs(O4,     make_float4(nv[0],nv[1],nv[2],nv[3]));
        __stcs(O4 + 1, make_float4(nv[4],nv[5],nv[6],nv[7]));
        float f[NR];
        #pragma unroll
        for (int r = 0; r < NR; r++){
            float s = 0.f;
            #pragma unroll
            for (int k = 0; k < 8; k++) s += nv[k]*rwj[r][k];
            f[r] = s;
        }
        // 8-lane butterfly only (12 shuffles instead of 20)
        #pragma unroll
        for (int off = 1; off < 8; off <<= 1)
            #pragma unroll
            for (int r = 0; r < NR; r++) f[r] += __shfl_xor_sync(0xffffffffu, f[r], off);
        if ((lane & 7) == 0){
            #pragma unroll
            for (int r = 0; r < NR; r++) sfwd[ii][r][slot] = f[r];
        }
        #pragma unroll
        for (int r = 0; r < NR; r++){
            float rwi = rwi_s[r][ii];
            #pragma unroll
            for (int k = 0; k < 8; k++) bwd[r][k] += rwi*nv[k];
        }
    }
    __syncthreads();
    {   // fwd: reduce 32 partials, direct store (this block owns these i)
        int ii = tid >> 2, r = tid & 3;
        float s = 0.f;
        #pragma unroll
        for (int w = 0; w < 32; w++) s += sfwd[ii][r][w];
        g_fwd[(b*NR+r)*NN + i0 + ii] = s;
    }
    #pragma unroll
    for (int r = 0; r < NR; r++)
        #pragma unroll
        for (int k = 0; k < 8; k++) atomicAdd(&g_bwd[(b*NR+r)*NN + jb + k], bwd[r][k]);
}

// ---- rw_new mix + read vectors (partial over 64-n chunks, atomics into out) ----
__global__ void k_rvrw(float* __restrict__ out){
    __shared__ float tile[64*WC];
    __shared__ float srw[NR*64];
    int b = blockIdx.x >> 5;
    int c = blockIdx.x & 31;
    int tid = threadIdx.x;
    int r = tid >> 6, idx = tid & 63;
    int n0 = c*64, n = n0 + idx;
    float m0r = g_rmraw[b*12 + r*3 + 0];
    float m1r = g_rmraw[b*12 + r*3 + 1];
    float m2r = g_rmraw[b*12 + r*3 + 2];
    float mx = fmaxf(m0r, fmaxf(m1r, m2r));
    float e0 = expf(m0r-mx), e1 = expf(m1r-mx), e2 = expf(m2r-mx);
    float inv = 1.f/(e0+e1+e2);
    int base = (b*NR+r)*NN;
    float rwv = e0*inv*g_bwd[base+n] + e1*inv*g_fwd[base+n] + e2*inv*g_rcw[base+n];
    out[OFF_RW + base + n] = rwv;
    srw[r*64 + idx] = rwv;
    for (int i = tid; i < 64*WC; i += 256)
        tile[i] = out[OFF_MEM + ((size_t)b*NN + n0)*WC + i];
    __syncthreads();
    float acc = 0.f;
    #pragma unroll 8
    for (int i = 0; i < 64; i++) acc += srw[r*64 + i]*tile[i*WC + idx];
    atomicAdd(&out[OFF_RV + b*256 + r*64 + idx], acc);
}

extern "C" void kernel_launch(void* const* d_in, const int* in_sizes, int n_in,
                              void* d_out, int out_size){
    const float* x        = (const float*)d_in[0];
    const float* memory   = (const float*)d_in[1];
    const float* link_old = (const float*)d_in[2];
    const float* prec     = (const float*)d_in[3];
    const float* rw_old   = (const float*)d_in[4];
    const float* ww_old   = (const float*)d_in[5];
    const float* usage0   = (const float*)d_in[6];
    CP cp;
    for (int s = 0; s < 10; s++){
        cp.W[s]    = (const float*)d_in[7 + 2*s];
        cp.bvec[s] = (const float*)d_in[8 + 2*s];
    }
    float* out = (float*)d_out;

    static cudaStream_t s1 = nullptr;
    static cudaEvent_t eC = nullptr, e1 = nullptr, eW = nullptr, e2 = nullptr;
    if (!s1){
        cudaStreamCreateWithFlags(&s1, cudaStreamNonBlocking);
        cudaEventCreateWithFlags(&eC, cudaEventDisableTiming);
        cudaEventCreateWithFlags(&e1, cudaEventDisableTiming);
        cudaEventCreateWithFlags(&eW, cudaEventDisableTiming);
        cudaEventCreateWithFlags(&e2, cudaEventDisableTiming);
    }

    // main stream: ctrl -> alloc -> ww -> link -> rvrw
    // side stream: zero + wcwlog (|| alloc), memnew + rcwsm (|| link)
    k_ctrl  <<<59, 256>>>(x, cp);
    cudaEventRecord(eC, 0);
    cudaStreamWaitEvent(s1, eC, 0);

    k_alloc <<<NB, 1024>>>(usage0, ww_old, rw_old, out);         // main
    k_zero  <<<(NB*NR*NN + NB*NR*WC + 255)/256, 256, 0, s1>>>(out);  // side
    k_wcwlog<<<NB*8, 256, 0, s1>>>(memory);                       // side
    cudaEventRecord(e1, s1);
    cudaStreamWaitEvent(0, e1, 0);

    k_ww    <<<NB, 256>>>(prec, out);                             // main
    cudaEventRecord(eW, 0);
    cudaStreamWaitEvent(s1, eW, 0);

    k_link  <<<dim3(NN/TI, NB), 256>>>(link_old, prec, rw_old, out);  // main (big)
    k_memnew<<<NB*256, 256, 0, s1>>>(memory, out);                // side
    k_rcwsm <<<NB*NR, 256, 0, s1>>>();                            // side
    cudaEventRecord(e2, s1);
    cudaStreamWaitEvent(0, e2, 0);

    k_rvrw  <<<NB*32, 256>>>(out);                                // main
}

// round 4
// speedup vs baseline: 1.9673x; 1.0466x over previous
#include <cuda_runtime.h>
#include <math.h>

#define NB 16
#define NN 2048
#define WC 64
#define NR 4
#define NI 512
#define DELTAF 1e-6f
#define TI 128

// ---- output offsets (flattened tuple order) ----
#define OFF_RV    0
#define OFF_MEM   (NB*NR*WC)                 // 4096
#define OFF_LINK  (OFF_MEM + NB*NN*WC)       // 2101248
#define OFF_PREC  (OFF_LINK + NB*NN*NN)      // 69210112
#define OFF_RW    (OFF_PREC + NB*NN)         // 69242880
#define OFF_WW    (OFF_RW + NB*NR*NN)        // 69373952
#define OFF_USAGE (OFF_WW + NB*NN)           // 69406720

// ---- device scratch ----
__device__ float g_readkeys[NB*NR*WC];
__device__ float g_rs[NB*NR];
__device__ float g_wkey[NB*WC];
__device__ float g_wstr[NB];
__device__ float g_ev[NB*WC];
__device__ float g_wv[NB*WC];
__device__ float g_fg[NB*NR];
__device__ float g_ag[NB];
__device__ float g_wg[NB];
__device__ float g_rmraw[NB*12];
__device__ float g_wcwlog[NB*NN];
__device__ float g_alloc[NB*NN];
__device__ float g_fwd[NB*NR*NN];   // direct stores
__device__ float g_bwd[NB*NR*NN];   // atomic accumulated
__device__ float g_rcw[NB*NR*NN];   // logits -> softmaxed in place

struct CP { const float* W[10]; const float* bvec[10]; };

__device__ __forceinline__ float act_apply(int code, float v){
    switch(code){
        case 0: return tanhf(v);
        case 1: return fmaxf(v, 0.f) + log1pf(expf(-fabsf(v)));  // softplus
        case 2: return 1.f/(1.f + expf(-v));                      // sigmoid
        default: return v;
    }
}

__device__ __forceinline__ float* seg_out(int seg){
    switch(seg){
        case 0: return g_readkeys;
        case 1: return g_rs;
        case 2: return g_wkey;
        case 3: return g_wstr;
        case 4: return g_ev;
        case 5: return g_wv;
        case 6: return g_fg;
        case 7: return g_ag;
        case 8: return g_wg;
        default: return g_rmraw;
    }
}

// ---- controller projections: one warp per output row (471 rows) ----
__global__ void k_ctrl(const float* __restrict__ x, CP cp){
    __shared__ float sx[NB*NI];
    int tid = threadIdx.x;
    for (int i = tid; i < NB*NI; i += blockDim.x) sx[i] = x[i];
    __syncthreads();
    int gw = (blockIdx.x*blockDim.x + tid) >> 5;
    int lane = tid & 31;
    if (gw >= 471) return;
    const int segStart[10] = {0,256,260,324,325,389,453,457,458,459};
    const int segLen[10]   = {256,4,64,1,64,64,4,1,1,12};
    const int segAct[10]   = {0,1,0,1,2,0,2,2,2,3};
    int seg = 0;
    for (int s = 9; s >= 0; s--){ if (gw >= segStart[s]){ seg = s; break; } }
    int rl = gw - segStart[seg];
    const float* W = cp.W[seg] + rl*NI;
    float wreg[16];
    #pragma unroll
    for (int s = 0; s < 16; s++) wreg[s] = W[s*32 + lane];
    float bias = cp.bvec[seg][rl];
    float* outp = seg_out(seg);
    int sl = segLen[seg], ac = segAct[seg];
    for (int b = 0; b < NB; b++){
        const float* xb = &sx[b*NI];
        float sum = 0.f;
        #pragma unroll
        for (int s = 0; s < 16; s++) sum += wreg[s]*xb[s*32 + lane];
        #pragma unroll
        for (int off = 16; off; off >>= 1) sum += __shfl_xor_sync(0xffffffffu, sum, off);
        if (lane == 0) outp[b*sl + rl] = act_apply(ac, sum + bias);
    }
}

// ---- write-content logits (+ folded zeroing of bwd / RV region) ----
__global__ void k_wcwlog(const float* __restrict__ mem, float* __restrict__ out){
    __shared__ float skey[WC];
    int b = blockIdx.x >> 3;
    int c = blockIdx.x & 7;
    int tid = threadIdx.x;
    // folded zero: 32768 threads cover bwd (131072) + RV (4096)
    {
        int gt = blockIdx.x*256 + tid;
        #pragma unroll
        for (int k = 0; k < 4; k++) g_bwd[k*32768 + gt] = 0.f;
        if (gt < NB*NR*WC) out[OFF_RV + gt] = 0.f;
    }
    if (tid < WC) skey[tid] = g_wkey[b*WC + tid];
    __syncthreads();
    float kn2 = 0.f;
    #pragma unroll
    for (int i = 0; i < WC; i++) kn2 += skey[i]*skey[i];
    float kn = sqrtf(kn2);
    float beta = g_wstr[b];
    int n = c*256 + tid;
    const float4* row = (const float4*)(mem + ((size_t)b*NN + n)*WC);
    float dot = 0.f, sq = 0.f;
    #pragma unroll
    for (int i = 0; i < WC/4; i++){
        float4 m = row[i];
        dot += m.x*skey[4*i] + m.y*skey[4*i+1] + m.z*skey[4*i+2] + m.w*skey[4*i+3];
        sq  += m.x*m.x + m.y*m.y + m.z*m.z + m.w*m.w;
    }
    g_wcwlog[b*NN + n] = beta*dot/(kn*sqrtf(sq) + DELTAF);
}

// ---- usage + allocation weighting: 32-bit-key bitonic sort + shuffle scan ----
__global__ void __launch_bounds__(1024)
k_alloc(const float* __restrict__ u0v, const float* __restrict__ wwold,
        const float* __restrict__ rwold, float* __restrict__ out){
    __shared__ unsigned keys[NN];
    __shared__ float su[NN];
    __shared__ float warptot[32];
    __shared__ float warpoff[32];
    int b = blockIdx.x, tid = threadIdx.x;   // 1024 threads
    int lane = tid & 31, wid = tid >> 5;
    for (int i = tid; i < NN; i += 1024){
        float u0 = u0v[b*NN + i];
        float u = u0 + (1.f - u0)*wwold[b*NN + i];
        float ret = 1.f;
        #pragma unroll
        for (int r = 0; r < NR; r++) ret *= (1.f - g_fg[b*NR+r]*rwold[(b*NR+r)*NN + i]);
        float usage = u*ret;
        out[OFF_USAGE + b*NN + i] = usage;
        float uu = DELTAF + (1.f - DELTAF)*usage;
        su[i] = uu;
        keys[i] = (__float_as_uint(uu) & 0xFFFFF800u) | (unsigned)i;
    }
    __syncthreads();
    for (int k = 2; k <= NN; k <<= 1){
        for (int j = k >> 1; j > 0; j >>= 1){
            #pragma unroll
            for (int h = 0; h < 2; h++){
                int i = h*1024 + tid;
                int ixj = i ^ j;
                if (ixj > i){
                    bool up = ((i & k) == 0);
                    unsigned a = keys[i], c = keys[ixj];
                    if (up ? (a > c) : (a < c)){ keys[i] = c; keys[ixj] = a; }
                }
            }
            if (j >= 32) __syncthreads(); else __syncwarp();
        }
        if (k >= 32) __syncthreads();
    }
    __syncthreads();
    // exclusive prefix product over sorted exact u (2 elems/thread)
    unsigned k0 = keys[2*tid], k1 = keys[2*tid + 1];
    float u0s = su[k0 & 0x7FFu];
    float u1s = su[k1 & 0x7FFu];
    float incl = u0s*u1s;
    #pragma unroll
    for (int d = 1; d < 32; d <<= 1){
        float v = __shfl_up_sync(0xffffffffu, incl, d);
        if (lane >= d) incl *= v;
    }
    if (lane == 31) warptot[wid] = incl;
    __syncthreads();
    if (wid == 0){
        float winc = warptot[lane];
        #pragma unroll
        for (int d = 1; d < 32; d <<= 1){
            float v = __shfl_up_sync(0xffffffffu, winc, d);
            if (lane >= d) winc *= v;
        }
        float wex = __shfl_up_sync(0xffffffffu, winc, 1);
        if (lane == 0) wex = 1.f;
        warpoff[lane] = wex;
    }
    __syncthreads();
    float excl = __shfl_up_sync(0xffffffffu, incl, 1);
    if (lane == 0) excl = 1.f;
    float pre0 = warpoff[wid]*excl;
    float pre1 = pre0*u0s;
    g_alloc[b*NN + (k0 & 0x7FFu)] = (1.f - u0s)*pre0;
    g_alloc[b*NN + (k1 & 0x7FFu)] = (1.f - u1s)*pre1;
}

// ---- wcw softmax + ww + precedence (per batch) ----
__global__ void k_ww(const float* __restrict__ prec_old, float* __restrict__ out){
    __shared__ float sl[NN];
    __shared__ float rbuf[256];
    int b = blockIdx.x, tid = threadIdx.x;
    float mx = -1e30f;
    #pragma unroll
    for (int k = 0; k < 8; k++){
        float v = g_wcwlog[b*NN + k*256 + tid];
        sl[k*256 + tid] = v;
        mx = fmaxf(mx, v);
    }
    rbuf[tid] = mx; __syncthreads();
    for (int s = 128; s; s >>= 1){ if (tid < s) rbuf[tid] = fmaxf(rbuf[tid], rbuf[tid+s]); __syncthreads(); }
    mx = rbuf[0]; __syncthreads();
    float sum = 0.f;
    #pragma unroll
    for (int k = 0; k < 8; k++){
        float e = expf(sl[k*256 + tid] - mx);
        sl[k*256 + tid] = e; sum += e;
    }
    rbuf[tid] = sum; __syncthreads();
    for (int s = 128; s; s >>= 1){ if (tid < s) rbuf[tid] += rbuf[tid+s]; __syncthreads(); }
    float inv = 1.f/rbuf[0];
    __syncthreads();
    float agv = g_ag[b], wgv = g_wg[b];
    float wwv[8], s2 = 0.f;
    #pragma unroll
    for (int k = 0; k < 8; k++){
        int n = k*256 + tid;
        float w = wgv*(agv*g_alloc[b*NN+n] + (1.f-agv)*sl[n]*inv);
        wwv[k] = w; s2 += w;
        out[OFF_WW + b*NN + n] = w;
    }
    rbuf[tid] = s2; __syncthreads();
    for (int st = 128; st; st >>= 1){ if (tid < st) rbuf[tid] += rbuf[tid+st]; __syncthreads(); }
    float S = rbuf[0];
    #pragma unroll
    for (int k = 0; k < 8; k++){
        int n = k*256 + tid;
        out[OFF_PREC + b*NN + n] = (1.f - S)*prec_old[b*NN + n] + wwv[k];
    }
}

// ---- memory update + read-content logits (fused), one warp per row ----
__global__ void k_memnew(const float* __restrict__ mem, float* __restrict__ out){
    __shared__ float skey[NR*WC];
    __shared__ float sknorm[NR];
    __shared__ float sev[WC], swv[WC];
    int b = blockIdx.x >> 8;
    int rowblk = blockIdx.x & 255;
    int tid = threadIdx.x;
    skey[tid] = g_readkeys[b*NR*WC + tid];
    if (tid < WC){ sev[tid] = g_ev[b*WC + tid]; swv[tid] = g_wv[b*WC + tid]; }
    __syncthreads();
    if (tid < NR){
        float s = 0.f;
        #pragma unroll
        for (int i = 0; i < WC; i++){ float v = skey[tid*WC + i]; s += v*v; }
        sknorm[tid] = sqrtf(s);
    }
    __syncthreads();
    int wrp = tid >> 5, lane = tid & 31;
    int n = rowblk*8 + wrp;
    int row = b*NN + n;
    int w0 = lane*2;
    float2 m = *(const float2*)(mem + (size_t)row*WC + w0);
    float ww = out[OFF_WW + row];
    float n0 = m.x*(1.f - ww*sev[w0])   + ww*swv[w0];
    float n1 = m.y*(1.f - ww*sev[w0+1]) + ww*swv[w0+1];
    *(float2*)(out + OFF_MEM + (size_t)row*WC + w0) = make_float2(n0, n1);
    float d[NR], sq = n0*n0 + n1*n1;
    #pragma unroll
    for (int r = 0; r < NR; r++) d[r] = n0*skey[r*WC + w0] + n1*skey[r*WC + w0 + 1];
    #pragma unroll
    for (int off = 16; off; off >>= 1){
        sq += __shfl_xor_sync(0xffffffffu, sq, off);
        #pragma unroll
        for (int r = 0; r < NR; r++) d[r] += __shfl_xor_sync(0xffffffffu, d[r], off);
    }
    if (lane == 0){
        float mn = sqrtf(sq);
        #pragma unroll
        for (int r = 0; r < NR; r++)
            g_rcw[(b*NR+r)*NN + n] = g_rs[b*NR+r]*d[r]/(sknorm[r]*mn + DELTAF);
    }
}

// ---- read-content softmax (in place), one block per (b,r) ----
__global__ void k_rcwsm(){
    __shared__ float sl[NN];
    __shared__ float rbuf[256];
    int base = blockIdx.x*NN;
    int tid = threadIdx.x;
    float mx = -1e30f;
    #pragma unroll
    for (int k = 0; k < 8; k++){
        float v = g_rcw[base + k*256 + tid];
        sl[k*256 + tid] = v;
        mx = fmaxf(mx, v);
    }
    rbuf[tid] = mx; __syncthreads();
    for (int s = 128; s; s >>= 1){ if (tid < s) rbuf[tid] = fmaxf(rbuf[tid], rbuf[tid+s]); __syncthreads(); }
    mx = rbuf[0]; __syncthreads();
    float sum = 0.f;
    #pragma unroll
    for (int k = 0; k < 8; k++){
        float e = expf(sl[k*256 + tid] - mx);
        sl[k*256 + tid] = e; sum += e;
    }
    rbuf[tid] = sum; __syncthreads();
    for (int s = 128; s; s >>= 1){ if (tid < s) rbuf[tid] += rbuf[tid+s]; __syncthreads(); }
    float inv = 1.f/rbuf[0];
    #pragma unroll
    for (int k = 0; k < 8; k++) g_rcw[base + k*256 + tid] = sl[k*256 + tid]*inv;
}

// ---- fused link update + fwd/bwd einsums (single pass over L) ----
__global__ void __launch_bounds__(256, 2)
k_link(const float* __restrict__ link_old, const float* __restrict__ prec_old,
       const float* __restrict__ rw_old, float* __restrict__ out){
    __shared__ float wwi_s[TI];
    __shared__ float rwi_s[NR][TI];
    __shared__ float sfwd[TI][NR][17];   // 16 partials + pad
    int b = blockIdx.y;
    int i0 = blockIdx.x * TI;
    int tid = threadIdx.x;
    int wrp = tid >> 5, lane = tid & 31;
    if (tid < TI) wwi_s[tid] = out[OFF_WW + b*NN + i0 + tid];
    #pragma unroll
    for (int h = 0; h < NR*TI/256; h++){
        int t = h*256 + tid;
        int r = t >> 7, ii = t & 127;
        rwi_s[r][ii] = rw_old[(b*NR+r)*NN + i0 + ii];
    }
    int jb = tid * 8;
    float wwj[8], pj[8], rwj[NR][8];
    #pragma unroll
    for (int k = 0; k < 8; k++){
        wwj[k] = out[OFF_WW + b*NN + jb + k];
        pj[k]  = prec_old[b*NN + jb + k];
    }
    #pragma unroll
    for (int r = 0; r < NR; r++)
        #pragma unroll
        for (int k = 0; k < 8; k++) rwj[r][k] = rw_old[(b*NR+r)*NN + jb + k];
    float bwd[NR][8];
    #pragma unroll
    for (int r = 0; r < NR; r++)
        #pragma unroll
        for (int k = 0; k < 8; k++) bwd[r][k] = 0.f;
    __syncthreads();
    const float* Lb = link_old + ((size_t)b*NN + i0)*NN + jb;
    float* Ob = out + OFF_LINK + ((size_t)b*NN + i0)*NN + jb;
    int slot = wrp*2 + (lane >> 4);   // 16 slots (16-lane groups)
    #pragma unroll 4
    for (int ii = 0; ii < TI; ii++){
        int i = i0 + ii;
        float wwi = wwi_s[ii];
        const float4* L4 = (const float4*)(Lb + (size_t)ii*NN);
        float4 o0 = __ldcs(L4);
        float4 o1 = __ldcs(L4 + 1);
        float old[8] = {o0.x,o0.y,o0.z,o0.w,o1.x,o1.y,o1.z,o1.w};
        float nv[8];
        #pragma unroll
        for (int k = 0; k < 8; k++){
            float v = (1.f - wwi - wwj[k])*old[k] + wwi*pj[k];
            if (jb + k == i) v = 0.f;
            nv[k] = v;
        }
        float4* O4 = (float4*)(Ob + (size_t)ii*NN);
        __stcs(O4,     make_float4(nv[0],nv[1],nv[2],nv[3]));
        __stcs(O4 + 1, make_float4(nv[4],nv[5],nv[6],nv[7]));
        float f[NR];
        #pragma unroll
        for (int r = 0; r < NR; r++){
            float s = 0.f;
            #pragma unroll
            for (int k = 0; k < 8; k++) s += nv[k]*rwj[r][k];
            f[r] = s;
        }
        // 16-lane butterfly (4 stages)
        #pragma unroll
        for (int off = 1; off < 16; off <<= 1)
            #pragma unroll
            for (int r = 0; r < NR; r++) f[r] += __shfl_xor_sync(0xffffffffu, f[r], off);
        if ((lane & 15) == 0){
            #pragma unroll
            for (int r = 0; r < NR; r++) sfwd[ii][r][slot] = f[r];
        }
        #pragma unroll
        for (int r = 0; r < NR; r++){
            float rwi = rwi_s[r][ii];
            #pragma unroll
            for (int k = 0; k < 8; k++) bwd[r][k] += rwi*nv[k];
        }
    }
    __syncthreads();
    {   // fwd: reduce 16 partials for 128 rows x 4 r = 512 outputs, 2 per thread
        #pragma unroll
        for (int h = 0; h < 2; h++){
            int t = h*256 + tid;
            int ii = t >> 2, r = t & 3;
            float s = 0.f;
            #pragma unroll
            for (int w = 0; w < 16; w++) s += sfwd[ii][r][w];
            g_fwd[(b*NR+r)*NN + i0 + ii] = s;
        }
    }
    #pragma unroll
    for (int r = 0; r < NR; r++)
        #pragma unroll
        for (int k = 0; k < 8; k++) atomicAdd(&g_bwd[(b*NR+r)*NN + jb + k], bwd[r][k]);
}

// ---- rw_new mix + read vectors (partial over 64-n chunks, atomics into out) ----
__global__ void k_rvrw(float* __restrict__ out){
    __shared__ float tile[64*WC];
    __shared__ float srw[NR*64];
    int b = blockIdx.x >> 5;
    int c = blockIdx.x & 31;
    int tid = threadIdx.x;
    int r = tid >> 6, idx = tid & 63;
    int n0 = c*64, n = n0 + idx;
    float m0r = g_rmraw[b*12 + r*3 + 0];
    float m1r = g_rmraw[b*12 + r*3 + 1];
    float m2r = g_rmraw[b*12 + r*3 + 2];
    float mx = fmaxf(m0r, fmaxf(m1r, m2r));
    float e0 = expf(m0r-mx), e1 = expf(m1r-mx), e2 = expf(m2r-mx);
    float inv = 1.f/(e0+e1+e2);
    int base = (b*NR+r)*NN;
    float rwv = e0*inv*g_bwd[base+n] + e1*inv*g_fwd[base+n] + e2*inv*g_rcw[base+n];
    out[OFF_RW + base + n] = rwv;
    srw[r*64 + idx] = rwv;
    for (int i = tid; i < 64*WC; i += 256)
        tile[i] = out[OFF_MEM + ((size_t)b*NN + n0)*WC + i];
    __syncthreads();
    float acc = 0.f;
    #pragma unroll 8
    for (int i = 0; i < 64; i++) acc += srw[r*64 + i]*tile[i*WC + idx];
    atomicAdd(&out[OFF_RV + b*256 + r*64 + idx], acc);
}

extern "C" void kernel_launch(void* const* d_in, const int* in_sizes, int n_in,
                              void* d_out, int out_size){
    const float* x        = (const float*)d_in[0];
    const float* memory   = (const float*)d_in[1];
    const float* link_old = (const float*)d_in[2];
    const float* prec     = (const float*)d_in[3];
    const float* rw_old   = (const float*)d_in[4];
    const float* ww_old   = (const float*)d_in[5];
    const float* usage0   = (const float*)d_in[6];
    CP cp;
    for (int s = 0; s < 10; s++){
        cp.W[s]    = (const float*)d_in[7 + 2*s];
        cp.bvec[s] = (const float*)d_in[8 + 2*s];
    }
    float* out = (float*)d_out;

    static cudaStream_t s1 = nullptr;
    static cudaEvent_t eC = nullptr, e1 = nullptr, eW = nullptr, e2 = nullptr;
    if (!s1){
        cudaStreamCreateWithFlags(&s1, cudaStreamNonBlocking);
        cudaEventCreateWithFlags(&eC, cudaEventDisableTiming);
        cudaEventCreateWithFlags(&e1, cudaEventDisableTiming);
        cudaEventCreateWithFlags(&eW, cudaEventDisableTiming);
        cudaEventCreateWithFlags(&e2, cudaEventDisableTiming);
    }

    // main stream: ctrl -> alloc -> ww -> link -> rvrw
    // side stream: wcwlog(+zero) (|| alloc), memnew + rcwsm (|| link)
    k_ctrl  <<<59, 256>>>(x, cp);
    cudaEventRecord(eC, 0);
    cudaStreamWaitEvent(s1, eC, 0);

    k_alloc <<<NB, 1024>>>(usage0, ww_old, rw_old, out);          // main
    k_wcwlog<<<NB*8, 256, 0, s1>>>(memory, out);                  // side (+zero)
    cudaEventRecord(e1, s1);
    cudaStreamWaitEvent(0, e1, 0);

    k_ww    <<<NB, 256>>>(prec, out);                             // main
    cudaEventRecord(eW, 0);
    cudaStreamWaitEvent(s1, eW, 0);

    k_link  <<<dim3(NN/TI, NB), 256>>>(link_old, prec, rw_old, out);  // main (big)
    k_memnew<<<NB*256, 256, 0, s1>>>(memory, out);                // side
    k_rcwsm <<<NB*NR, 256, 0, s1>>>();                            // side
    cudaEventRecord(e2, s1);
    cudaStreamWaitEvent(0, e2, 0);

    k_rvrw  <<<NB*32, 256>>>(out);                                // main
}

// round 6
// speedup vs baseline: 2.0625x; 1.0484x over previous
#include <cuda_runtime.h>
#include <math.h>

#define NB 16
#define NN 2048
#define WC 64
#define NR 4
#define NI 512
#define DELTAF 1e-6f
#define TI 128

// ---- output offsets (flattened tuple order) ----
#define OFF_RV    0
#define OFF_MEM   (NB*NR*WC)                 // 4096
#define OFF_LINK  (OFF_MEM + NB*NN*WC)       // 2101248
#define OFF_PREC  (OFF_LINK + NB*NN*NN)      // 69210112
#define OFF_RW    (OFF_PREC + NB*NN)         // 69242880
#define OFF_WW    (OFF_RW + NB*NR*NN)        // 69373952
#define OFF_USAGE (OFF_WW + NB*NN)           // 69406720

// ---- device scratch ----
__device__ float g_readkeys[NB*NR*WC];
__device__ float g_rs[NB*NR];
__device__ float g_wkey[NB*WC];
__device__ float g_wstr[NB];
__device__ float g_ev[NB*WC];
__device__ float g_wv[NB*WC];
__device__ float g_fg[NB*NR];
__device__ float g_ag[NB];
__device__ float g_wg[NB];
__device__ float g_rmraw[NB*12];
__device__ float g_wcwlog[NB*NN];   // exp(logit) values
__device__ float g_wcwsum[NB];      // per-batch sum of exp
__device__ float g_alloc[NB*NN];
__device__ float g_fwd[NB*NR*NN];   // direct stores
__device__ float g_bwd[NB*NR*NN];   // atomic accumulated
__device__ float g_rcw[NB*NR*NN];   // logits -> softmaxed in place

struct CP { const float* W[10]; const float* bvec[10]; };

__device__ __forceinline__ float act_apply(int code, float v){
    switch(code){
        case 0: return tanhf(v);
        case 1: return fmaxf(v, 0.f) + log1pf(expf(-fabsf(v)));  // softplus
        case 2: return 1.f/(1.f + expf(-v));                      // sigmoid
        default: return v;
    }
}

__device__ __forceinline__ float* seg_out(int seg){
    switch(seg){
        case 0: return g_readkeys;
        case 1: return g_rs;
        case 2: return g_wkey;
        case 3: return g_wstr;
        case 4: return g_ev;
        case 5: return g_wv;
        case 6: return g_fg;
        case 7: return g_ag;
        case 8: return g_wg;
        default: return g_rmraw;
    }
}

// ---- controller projections: one warp per output row (471 rows) ----
__global__ void k_ctrl(const float* __restrict__ x, CP cp){
    __shared__ float sx[NB*NI];
    int tid = threadIdx.x;
    if (blockIdx.x == 0 && tid < NB) g_wcwsum[tid] = 0.f;   // zero before wcwlog atomics
    for (int i = tid; i < NB*NI; i += blockDim.x) sx[i] = x[i];
    __syncthreads();
    int gw = (blockIdx.x*blockDim.x + tid) >> 5;
    int lane = tid & 31;
    if (gw >= 471) return;
    const int segStart[10] = {0,256,260,324,325,389,453,457,458,459};
    const int segLen[10]   = {256,4,64,1,64,64,4,1,1,12};
    const int segAct[10]   = {0,1,0,1,2,0,2,2,2,3};
    int seg = 0;
    for (int s = 9; s >= 0; s--){ if (gw >= segStart[s]){ seg = s; break; } }
    int rl = gw - segStart[seg];
    const float* W = cp.W[seg] + rl*NI;
    float wreg[16];
    #pragma unroll
    for (int s = 0; s < 16; s++) wreg[s] = W[s*32 + lane];
    float bias = cp.bvec[seg][rl];
    float* outp = seg_out(seg);
    int sl = segLen[seg], ac = segAct[seg];
    for (int b = 0; b < NB; b++){
        const float* xb = &sx[b*NI];
        float sum = 0.f;
        #pragma unroll
        for (int s = 0; s < 16; s++) sum += wreg[s]*xb[s*32 + lane];
        #pragma unroll
        for (int off = 16; off; off >>= 1) sum += __shfl_xor_sync(0xffffffffu, sum, off);
        if (lane == 0) outp[b*sl + rl] = act_apply(ac, sum + bias);
    }
}

// ---- write-content exp(logits) + per-batch sum (+ folded zeroing) ----
__global__ void k_wcwlog(const float* __restrict__ mem, float* __restrict__ out){
    __shared__ float skey[WC];
    __shared__ float rbuf[8];
    int b = blockIdx.x >> 3;
    int c = blockIdx.x & 7;
    int tid = threadIdx.x;
    int lane = tid & 31, wid = tid >> 5;
    // folded zero: 32768 threads cover bwd (131072) + RV (4096)
    {
        int gt = blockIdx.x*256 + tid;
        #pragma unroll
        for (int k = 0; k < 4; k++) g_bwd[k*32768 + gt] = 0.f;
        if (gt < NB*NR*WC) out[OFF_RV + gt] = 0.f;
    }
    if (tid < WC) skey[tid] = g_wkey[b*WC + tid];
    __syncthreads();
    float kn2 = 0.f;
    #pragma unroll
    for (int i = 0; i < WC; i++) kn2 += skey[i]*skey[i];
    float kn = sqrtf(kn2);
    float beta = g_wstr[b];
    int n = c*256 + tid;
    const float4* row = (const float4*)(mem + ((size_t)b*NN + n)*WC);
    float dot = 0.f, sq = 0.f;
    #pragma unroll
    for (int i = 0; i < WC/4; i++){
        float4 m = row[i];
        dot += m.x*skey[4*i] + m.y*skey[4*i+1] + m.z*skey[4*i+2] + m.w*skey[4*i+3];
        sq  += m.x*m.x + m.y*m.y + m.z*m.z + m.w*m.w;
    }
    // no max-subtraction: |logit| <= beta (cos-sim in [-1,1]), exp safe in fp32
    float e = expf(beta*dot/(kn*sqrtf(sq) + DELTAF));
    g_wcwlog[b*NN + n] = e;
    float s = e;
    #pragma unroll
    for (int off = 16; off; off >>= 1) s += __shfl_xor_sync(0xffffffffu, s, off);
    if (lane == 0) rbuf[wid] = s;
    __syncthreads();
    if (tid == 0){
        float t = 0.f;
        #pragma unroll
        for (int w = 0; w < 8; w++) t += rbuf[w];
        atomicAdd(&g_wcwsum[b], t);
    }
}

// ---- usage + allocation (free gates computed inline; no ctrl dependency) ----
__global__ void __launch_bounds__(1024)
k_alloc(const float* __restrict__ u0v, const float* __restrict__ wwold,
        const float* __restrict__ rwold, const float* __restrict__ x,
        const float* __restrict__ W_fg, const float* __restrict__ b_fg,
        float* __restrict__ out){
    __shared__ unsigned keys[NN];
    __shared__ float su[NN];
    __shared__ float warptot[32];
    __shared__ float warpoff[32];
    __shared__ float sfg[NR];
    int b = blockIdx.x, tid = threadIdx.x;   // 1024 threads
    int lane = tid & 31, wid = tid >> 5;
    // free gates for this batch: warps 0-3, one r each
    if (wid < NR){
        int r = wid;
        float s = 0.f;
        #pragma unroll
        for (int i = 0; i < 16; i++)
            s += x[b*NI + i*32 + lane]*W_fg[r*NI + i*32 + lane];
        #pragma unroll
        for (int off = 16; off; off >>= 1) s += __shfl_xor_sync(0xffffffffu, s, off);
        if (lane == 0) sfg[r] = 1.f/(1.f + expf(-(s + b_fg[r])));
    }
    __syncthreads();
    for (int i = tid; i < NN; i += 1024){
        float u0 = u0v[b*NN + i];
        float u = u0 + (1.f - u0)*wwold[b*NN + i];
        float ret = 1.f;
        #pragma unroll
        for (int r = 0; r < NR; r++) ret *= (1.f - sfg[r]*rwold[(b*NR+r)*NN + i]);
        float usage = u*ret;
        out[OFF_USAGE + b*NN + i] = usage;
        float uu = DELTAF + (1.f - DELTAF)*usage;
        su[i] = uu;
        keys[i] = (__float_as_uint(uu) & 0xFFFFF800u) | (unsigned)i;
    }
    __syncthreads();
    for (int k = 2; k <= NN; k <<= 1){
        for (int j = k >> 1; j > 0; j >>= 1){
            #pragma unroll
            for (int h = 0; h < 2; h++){
                int i = h*1024 + tid;
                int ixj = i ^ j;
                if (ixj > i){
                    bool up = ((i & k) == 0);
                    unsigned a = keys[i], c = keys[ixj];
                    if (up ? (a > c) : (a < c)){ keys[i] = c; keys[ixj] = a; }
                }
            }
            if (j >= 32) __syncthreads(); else __syncwarp();
        }
        if (k >= 32) __syncthreads();
    }
    __syncthreads();
    // exclusive prefix product over sorted exact u (2 elems/thread)
    unsigned k0 = keys[2*tid], k1 = keys[2*tid + 1];
    float u0s = su[k0 & 0x7FFu];
    float u1s = su[k1 & 0x7FFu];
    float incl = u0s*u1s;
    #pragma unroll
    for (int d = 1; d < 32; d <<= 1){
        float v = __shfl_up_sync(0xffffffffu, incl, d);
        if (lane >= d) incl *= v;
    }
    if (lane == 31) warptot[wid] = incl;
    __syncthreads();
    if (wid == 0){
        float winc = warptot[lane];
        #pragma unroll
        for (int d = 1; d < 32; d <<= 1){
            float v = __shfl_up_sync(0xffffffffu, winc, d);
            if (lane >= d) winc *= v;
        }
        float wex = __shfl_up_sync(0xffffffffu, winc, 1);
        if (lane == 0) wex = 1.f;
        warpoff[lane] = wex;
    }
    __syncthreads();
    float excl = __shfl_up_sync(0xffffffffu, incl, 1);
    if (lane == 0) excl = 1.f;
    float pre0 = warpoff[wid]*excl;
    float pre1 = pre0*u0s;
    g_alloc[b*NN + (k0 & 0x7FFu)] = (1.f - u0s)*pre0;
    g_alloc[b*NN + (k1 & 0x7FFu)] = (1.f - u1s)*pre1;
}

// ---- ww + precedence: single reduction (softmax sum precomputed) ----
__global__ void k_ww(const float* __restrict__ prec_old, float* __restrict__ out){
    __shared__ float rbuf[8];
    int b = blockIdx.x, tid = threadIdx.x;
    int lane = tid & 31, wid = tid >> 5;
    float inv = 1.f/g_wcwsum[b];
    float agv = g_ag[b], wgv = g_wg[b];
    float wwv[8], s2 = 0.f;
    #pragma unroll
    for (int k = 0; k < 8; k++){
        int n = k*256 + tid;
        float w = wgv*(agv*g_alloc[b*NN+n] + (1.f-agv)*g_wcwlog[b*NN+n]*inv);
        wwv[k] = w; s2 += w;
        out[OFF_WW + b*NN + n] = w;
    }
    #pragma unroll
    for (int off = 16; off; off >>= 1) s2 += __shfl_xor_sync(0xffffffffu, s2, off);
    if (lane == 0) rbuf[wid] = s2;
    __syncthreads();
    float S = 0.f;
    #pragma unroll
    for (int w = 0; w < 8; w++) S += rbuf[w];
    #pragma unroll
    for (int k = 0; k < 8; k++){
        int n = k*256 + tid;
        out[OFF_PREC + b*NN + n] = (1.f - S)*prec_old[b*NN + n] + wwv[k];
    }
}

// ---- memory update + read-content logits (fused), one warp per row ----
__global__ void k_memnew(const float* __restrict__ mem, float* __restrict__ out){
    __shared__ float skey[NR*WC];
    __shared__ float sknorm[NR];
    __shared__ float sev[WC], swv[WC];
    int b = blockIdx.x >> 8;
    int rowblk = blockIdx.x & 255;
    int tid = threadIdx.x;
    skey[tid] = g_readkeys[b*NR*WC + tid];
    if (tid < WC){ sev[tid] = g_ev[b*WC + tid]; swv[tid] = g_wv[b*WC + tid]; }
    __syncthreads();
    if (tid < NR){
        float s = 0.f;
        #pragma unroll
        for (int i = 0; i < WC; i++){ float v = skey[tid*WC + i]; s += v*v; }
        sknorm[tid] = sqrtf(s);
    }
    __syncthreads();
    int wrp = tid >> 5, lane = tid & 31;
    int n = rowblk*8 + wrp;
    int row = b*NN + n;
    int w0 = lane*2;
    float2 m = *(const float2*)(mem + (size_t)row*WC + w0);
    float ww = out[OFF_WW + row];
    float n0 = m.x*(1.f - ww*sev[w0])   + ww*swv[w0];
    float n1 = m.y*(1.f - ww*sev[w0+1]) + ww*swv[w0+1];
    *(float2*)(out + OFF_MEM + (size_t)row*WC + w0) = make_float2(n0, n1);
    float d[NR], sq = n0*n0 + n1*n1;
    #pragma unroll
    for (int r = 0; r < NR; r++) d[r] = n0*skey[r*WC + w0] + n1*skey[r*WC + w0 + 1];
    #pragma unroll
    for (int off = 16; off; off >>= 1){
        sq += __shfl_xor_sync(0xffffffffu, sq, off);
        #pragma unroll
        for (int r = 0; r < NR; r++) d[r] += __shfl_xor_sync(0xffffffffu, d[r], off);
    }
    if (lane == 0){
        float mn = sqrtf(sq);
        #pragma unroll
        for (int r = 0; r < NR; r++)
            g_rcw[(b*NR+r)*NN + n] = g_rs[b*NR+r]*d[r]/(sknorm[r]*mn + DELTAF);
    }
}

// ---- read-content softmax (in place), one block per (b,r) ----
__global__ void k_rcwsm(){
    __shared__ float sl[NN];
    __shared__ float rbuf[256];
    int base = blockIdx.x*NN;
    int tid = threadIdx.x;
    float mx = -1e30f;
    #pragma unroll
    for (int k = 0; k < 8; k++){
        float v = g_rcw[base + k*256 + tid];
        sl[k*256 + tid] = v;
        mx = fmaxf(mx, v);
    }
    rbuf[tid] = mx; __syncthreads();
    for (int s = 128; s; s >>= 1){ if (tid < s) rbuf[tid] = fmaxf(rbuf[tid], rbuf[tid+s]); __syncthreads(); }
    mx = rbuf[0]; __syncthreads();
    float sum = 0.f;
    #pragma unroll
    for (int k = 0; k < 8; k++){
        float e = expf(sl[k*256 + tid] - mx);
        sl[k*256 + tid] = e; sum += e;
    }
    rbuf[tid] = sum; __syncthreads();
    for (int s = 128; s; s >>= 1){ if (tid < s) rbuf[tid] += rbuf[tid+s]; __syncthreads(); }
    float inv = 1.f/rbuf[0];
    #pragma unroll
    for (int k = 0; k < 8; k++) g_rcw[base + k*256 + tid] = sl[k*256 + tid]*inv;
}

// ---- fused link update + fwd/bwd einsums (single pass over L) ----
__global__ void __launch_bounds__(256, 2)
k_link(const float* __restrict__ link_old, const float* __restrict__ prec_old,
       const float* __restrict__ rw_old, float* __restrict__ out){
    __shared__ float wwi_s[TI];
    __shared__ float rwi_s[NR][TI];
    __shared__ float sfwd[TI][NR][17];   // 16 partials + pad
    int b = blockIdx.y;
    int i0 = blockIdx.x * TI;
    int tid = threadIdx.x;
    int wrp = tid >> 5, lane = tid & 31;
    if (tid < TI) wwi_s[tid] = out[OFF_WW + b*NN + i0 + tid];
    #pragma unroll
    for (int h = 0; h < NR*TI/256; h++){
        int t = h*256 + tid;
        int r = t >> 7, ii = t & 127;
        rwi_s[r][ii] = rw_old[(b*NR+r)*NN + i0 + ii];
    }
    int jb = tid * 8;
    float wwj[8], pj[8], rwj[NR][8];
    #pragma unroll
    for (int k = 0; k < 8; k++){
        wwj[k] = out[OFF_WW + b*NN + jb + k];
        pj[k]  = prec_old[b*NN + jb + k];
    }
    #pragma unroll
    for (int r = 0; r < NR; r++)
        #pragma unroll
        for (int k = 0; k < 8; k++) rwj[r][k] = rw_old[(b*NR+r)*NN + jb + k];
    float bwd[NR][8];
    #pragma unroll
    for (int r = 0; r < NR; r++)
        #pragma unroll
        for (int k = 0; k < 8; k++) bwd[r][k] = 0.f;
    __syncthreads();
    const float* Lb = link_old + ((size_t)b*NN + i0)*NN + jb;
    float* Ob = out + OFF_LINK + ((size_t)b*NN + i0)*NN + jb;
    int slot = wrp*2 + (lane >> 4);   // 16 slots (16-lane groups)
    #pragma unroll 4
    for (int ii = 0; ii < TI; ii++){
        int i = i0 + ii;
        float wwi = wwi_s[ii];
        const float4* L4 = (const float4*)(Lb + (size_t)ii*NN);
        float4 o0 = __ldcs(L4);
        float4 o1 = __ldcs(L4 + 1);
        float old[8] = {o0.x,o0.y,o0.z,o0.w,o1.x,o1.y,o1.z,o1.w};
        float nv[8];
        #pragma unroll
        for (int k = 0; k < 8; k++){
            float v = (1.f - wwi - wwj[k])*old[k] + wwi*pj[k];
            if (jb + k == i) v = 0.f;
            nv[k] = v;
        }
        float4* O4 = (float4*)(Ob + (size_t)ii*NN);
        __stcs(O4,     make_float4(nv[0],nv[1],nv[2],nv[3]));
        __stcs(O4 + 1, make_float4(nv[4],nv[5],nv[6],nv[7]));
        float f[NR];
        #pragma unroll
        for (int r = 0; r < NR; r++){
            float s = 0.f;
            #pragma unroll
            for (int k = 0; k < 8; k++) s += nv[k]*rwj[r][k];
            f[r] = s;
        }
        // 16-lane butterfly (4 stages)
        #pragma unroll
        for (int off = 1; off < 16; off <<= 1)
            #pragma unroll
            for (int r = 0; r < NR; r++) f[r] += __shfl_xor_sync(0xffffffffu, f[r], off);
        if ((lane & 15) == 0){
            #pragma unroll
            for (int r = 0; r < NR; r++) sfwd[ii][r][slot] = f[r];
        }
        #pragma unroll
        for (int r = 0; r < NR; r++){
            float rwi = rwi_s[r][ii];
            #pragma unroll
            for (int k = 0; k < 8; k++) bwd[r][k] += rwi*nv[k];
        }
    }
    __syncthreads();
    {
        #pragma unroll
        for (int h = 0; h < 2; h++){
            int t = h*256 + tid;
            int ii = t >> 2, r = t & 3;
            float s = 0.f;
            #pragma unroll
            for (int w = 0; w < 16; w++) s += sfwd[ii][r][w];
            g_fwd[(b*NR+r)*NN + i0 + ii] = s;
        }
    }
    #pragma unroll
    for (int r = 0; r < NR; r++)
        #pragma unroll
        for (int k = 0; k < 8; k++) atomicAdd(&g_bwd[(b*NR+r)*NN + jb + k], bwd[r][k]);
}

// ---- rw_new mix + read vectors (partial over 64-n chunks, atomics into out) ----
__global__ void k_rvrw(float* __restrict__ out){
    __shared__ float tile[64*WC];
    __shared__ float srw[NR*64];
    int b = blockIdx.x >> 5;
    int c = blockIdx.x & 31;
    int tid = threadIdx.x;
    int r = tid >> 6, idx = tid & 63;
    int n0 = c*64, n = n0 + idx;
    float m0r = g_rmraw[b*12 + r*3 + 0];
    float m1r = g_rmraw[b*12 + r*3 + 1];
    float m2r = g_rmraw[b*12 + r*3 + 2];
    float mx = fmaxf(m0r, fmaxf(m1r, m2r));
    float e0 = expf(m0r-mx), e1 = expf(m1r-mx), e2 = expf(m2r-mx);
    float inv = 1.f/(e0+e1+e2);
    int base = (b*NR+r)*NN;
    float rwv = e0*inv*g_bwd[base+n] + e1*inv*g_fwd[base+n] + e2*inv*g_rcw[base+n];
    out[OFF_RW + base + n] = rwv;
    srw[r*64 + idx] = rwv;
    for (int i = tid; i < 64*WC; i += 256)
        tile[i] = out[OFF_MEM + ((size_t)b*NN + n0)*WC + i];
    __syncthreads();
    float acc = 0.f;
    #pragma unroll 8
    for (int i = 0; i < 64; i++) acc += srw[r*64 + i]*tile[i*WC + idx];
    atomicAdd(&out[OFF_RV + b*256 + r*64 + idx], acc);
}

extern "C" void kernel_launch(void* const* d_in, const int* in_sizes, int n_in,
                              void* d_out, int out_size){
    const float* x        = (const float*)d_in[0];
    const float* memory   = (const float*)d_in[1];
    const float* link_old = (const float*)d_in[2];
    const float* prec     = (const float*)d_in[3];
    const float* rw_old   = (const float*)d_in[4];
    const float* ww_old   = (const float*)d_in[5];
    const float* usage0   = (const float*)d_in[6];
    CP cp;
    for (int s = 0; s < 10; s++){
        cp.W[s]    = (const float*)d_in[7 + 2*s];
        cp.bvec[s] = (const float*)d_in[8 + 2*s];
    }
    const float* W_fg = cp.W[6];
    const float* b_fg = cp.bvec[6];
    float* out = (float*)d_out;

    static cudaStream_t s1 = nullptr;
    static cudaEvent_t eF = nullptr, e1 = nullptr, eW = nullptr, e2 = nullptr;
    if (!s1){
        cudaStreamCreateWithFlags(&s1, cudaStreamNonBlocking);
        cudaEventCreateWithFlags(&eF, cudaEventDisableTiming);
        cudaEventCreateWithFlags(&e1, cudaEventDisableTiming);
        cudaEventCreateWithFlags(&eW, cudaEventDisableTiming);
        cudaEventCreateWithFlags(&e2, cudaEventDisableTiming);
    }

    // FORK: side stream must join the capture via an event from the capture
    // stream BEFORE any launch on it.
    cudaEventRecord(eF, 0);
    cudaStreamWaitEvent(s1, eF, 0);

    // main stream: alloc -> ww -> link -> rvrw
    // side stream: ctrl -> wcwlog(+zero) (|| alloc), memnew -> rcwsm (|| link)
    k_alloc <<<NB, 1024>>>(usage0, ww_old, rw_old, x, W_fg, b_fg, out);  // main
    k_ctrl  <<<59, 256, 0, s1>>>(x, cp);                                 // side
    k_wcwlog<<<NB*8, 256, 0, s1>>>(memory, out);                         // side
    cudaEventRecord(e1, s1);
    cudaStreamWaitEvent(0, e1, 0);

    k_ww    <<<NB, 256>>>(prec, out);                                    // main
    cudaEventRecord(eW, 0);
    cudaStreamWaitEvent(s1, eW, 0);

    k_link  <<<dim3(NN/TI, NB), 256>>>(link_old, prec, rw_old, out);     // main (big)
    k_memnew<<<NB*256, 256, 0, s1>>>(memory, out);                       // side
    k_rcwsm <<<NB*NR, 256, 0, s1>>>();                                   // side
    cudaEventRecord(e2, s1);
    cudaStreamWaitEvent(0, e2, 0);

    k_rvrw  <<<NB*32, 256>>>(out);                                       // main
}